// round 3
// baseline (speedup 1.0000x reference)
#include <cuda_runtime.h>
#include <cuda_bf16.h>
#include <math.h>

#define T_TOK 2048
#define HDIM  1024
#define IDIM  512
#define NEXP  16
#define TOPK  4
#define RTOT  (T_TOK * TOPK)   // total routed rows = 8192 exactly

// ---------------- scratch (static device globals; no allocation) ----------------
__device__ int   g_cnt[NEXP];
__device__ int   g_off[NEXP];                         // exclusive prefix of g_cnt
__device__ int   g_tok[NEXP * T_TOK];
__device__ int   g_kk [NEXP * T_TOK];
__device__ float g_wgt[NEXP * T_TOK];
__device__ int   g_topk_idx[T_TOK * TOPK];
__device__ float g_topk_w [T_TOK * TOPK];
__device__ float g_act   [(size_t)RTOT * IDIM];       // 16 MB, compacted routed act
__device__ float g_act_s [(size_t)T_TOK * IDIM];      // 4 MB, shared-expert act
__device__ float g_part  [(size_t)RTOT * HDIM];       // 32 MB, per-(t,k) down output
__device__ float g_part_s[(size_t)T_TOK * HDIM];      // 8 MB, shared-expert down out

// ---------------- router: warp per token ----------------
__global__ void router_kernel(const float* __restrict__ X, const float* __restrict__ RW)
{
    int warp = threadIdx.x >> 5;
    int lane = threadIdx.x & 31;
    int t = blockIdx.x * 8 + warp;

    const float4* X4  = (const float4*)X;
    const float4* RW4 = (const float4*)RW;

    float acc[NEXP];
#pragma unroll
    for (int e = 0; e < NEXP; ++e) acc[e] = 0.f;

#pragma unroll
    for (int it = 0; it < 8; ++it) {
        int h4 = lane + it * 32;                  // float4 index in row (0..255)
        float4 xv = X4[(size_t)t * 256 + h4];
        int h = h4 * 4;
#pragma unroll
        for (int j = 0; j < 4; ++j) {
            float xs = (j == 0) ? xv.x : (j == 1) ? xv.y : (j == 2) ? xv.z : xv.w;
            float rw[NEXP];
#pragma unroll
            for (int q = 0; q < 4; ++q) {
                float4 rv = RW4[(size_t)(h + j) * 4 + q];
                rw[q*4+0] = rv.x; rw[q*4+1] = rv.y; rw[q*4+2] = rv.z; rw[q*4+3] = rv.w;
            }
#pragma unroll
            for (int e = 0; e < NEXP; ++e) acc[e] += xs * rw[e];
        }
    }
#pragma unroll
    for (int e = 0; e < NEXP; ++e) {
#pragma unroll
        for (int off = 16; off > 0; off >>= 1)
            acc[e] += __shfl_xor_sync(0xffffffffu, acc[e], off);
    }
    if (lane == 0) {
        float v[NEXP];
#pragma unroll
        for (int e = 0; e < NEXP; ++e) v[e] = 1.f / (1.f + expf(-acc[e]));
        bool used[NEXP];
#pragma unroll
        for (int e = 0; e < NEXP; ++e) used[e] = false;
        for (int k = 0; k < TOPK; ++k) {
            int best = -1; float bv = -1e30f;
            for (int e = 0; e < NEXP; ++e)
                if (!used[e] && v[e] > bv) { bv = v[e]; best = e; }
            used[best] = true;
            g_topk_idx[t * TOPK + k] = best;
            g_topk_w [t * TOPK + k] = bv;
        }
    }
}

// ---------------- deterministic per-expert compaction: block per expert ----------------
__global__ void lists_kernel()
{
    __shared__ int s[256];
    int e = blockIdx.x;
    int tid = threadIdx.x;
    int base = 0;
    for (int t0 = 0; t0 < T_TOK; t0 += 256) {
        int t = t0 + tid;
        int kk = -1; float w = 0.f;
#pragma unroll
        for (int k = 0; k < TOPK; ++k) {
            if (g_topk_idx[t * TOPK + k] == e) { kk = k; w = g_topk_w[t * TOPK + k]; }
        }
        int flag = (kk >= 0) ? 1 : 0;
        s[tid] = flag;
        __syncthreads();
        for (int off = 1; off < 256; off <<= 1) {
            int v = (tid >= off) ? s[tid - off] : 0;
            __syncthreads();
            s[tid] += v;
            __syncthreads();
        }
        int pos = s[tid] - flag;       // exclusive
        int total = s[255];
        if (flag) {
            int o = e * T_TOK + base + pos;
            g_tok[o] = t; g_kk[o] = kk; g_wgt[o] = w;
        }
        base += total;
        __syncthreads();
    }
    if (tid == 0) g_cnt[e] = base;
}

// ---------------- tiny exclusive prefix sum over 16 counts ----------------
__global__ void offsets_kernel()
{
    if (threadIdx.x == 0) {
        int run = 0;
        for (int e = 0; e < NEXP; ++e) { g_off[e] = run; run += g_cnt[e]; }
    }
}

__device__ __forceinline__ float silu_f(float g) { return g / (1.f + expf(-g)); }

// ---------------- fused gate+up+SiLU GEMM ----------------
// grid (32, 8, 17): x = M tile (64 rows), y = N tile over I, z = expert (16 = shared)
__global__ __launch_bounds__(256) void gemm_gu(
    const float* __restrict__ X,
    const float* __restrict__ GateW, const float* __restrict__ UpW,
    const float* __restrict__ SGateW, const float* __restrict__ SUpW)
{
    int ez = blockIdx.z;
    bool sh = (ez == NEXP);
    int n;
    const int* tok = nullptr;
    const float* wgt = nullptr;
    const float* Wg; const float* Wu; float* out;
    if (sh) { n = T_TOK; Wg = SGateW; Wu = SUpW; out = g_act_s; }
    else {
        n = g_cnt[ez];
        tok = &g_tok[ez * T_TOK]; wgt = &g_wgt[ez * T_TOK];
        Wg = GateW + (size_t)ez * HDIM * IDIM;
        Wu = UpW   + (size_t)ez * HDIM * IDIM;
        out = g_act + (size_t)g_off[ez] * IDIM;
    }
    int m0 = blockIdx.x * 64;
    if (m0 >= n) return;
    int n0 = blockIdx.y * 64;

    __shared__ float As[16][68];
    __shared__ float Bg[16][64];
    __shared__ float Bu[16][64];

    int tid = threadIdx.x;
    int tx = tid & 15, ty = tid >> 4;

    float accG[4][4], accU[4][4];
#pragma unroll
    for (int i = 0; i < 4; ++i)
#pragma unroll
        for (int j = 0; j < 4; ++j) { accG[i][j] = 0.f; accU[i][j] = 0.f; }

    int arow = tid >> 2, aquad = tid & 3;   // A tile: 64 rows x 4 quads of 4
    int brow = tid >> 4, bseg = tid & 15;   // B tile: 16 k-rows x 16 segs of 4

    int m_a = m0 + arow;
    const float* aptr = nullptr;
    float aw = 1.f;
    if (m_a < n) {
        int t = sh ? m_a : tok[m_a];
        aw = sh ? 1.f : wgt[m_a];
        aptr = X + (size_t)t * HDIM;
    }

    for (int k0 = 0; k0 < HDIM; k0 += 16) {
        float4 av = make_float4(0.f, 0.f, 0.f, 0.f);
        if (aptr) av = *(const float4*)(aptr + k0 + aquad * 4);
        av.x *= aw; av.y *= aw; av.z *= aw; av.w *= aw;
        As[aquad * 4 + 0][arow] = av.x;
        As[aquad * 4 + 1][arow] = av.y;
        As[aquad * 4 + 2][arow] = av.z;
        As[aquad * 4 + 3][arow] = av.w;
        {
            size_t boff = (size_t)(k0 + brow) * IDIM + n0 + bseg * 4;
            float4 bg = *(const float4*)(Wg + boff);
            float4 bu = *(const float4*)(Wu + boff);
            *(float4*)&Bg[brow][bseg * 4] = bg;
            *(float4*)&Bu[brow][bseg * 4] = bu;
        }
        __syncthreads();
#pragma unroll
        for (int kk = 0; kk < 16; ++kk) {
            float4 a4  = *(const float4*)&As[kk][ty * 4];
            float4 bgv = *(const float4*)&Bg[kk][tx * 4];
            float4 buv = *(const float4*)&Bu[kk][tx * 4];
            float a[4] = {a4.x, a4.y, a4.z, a4.w};
            float bgr[4] = {bgv.x, bgv.y, bgv.z, bgv.w};
            float bur[4] = {buv.x, buv.y, buv.z, buv.w};
#pragma unroll
            for (int i = 0; i < 4; ++i)
#pragma unroll
                for (int j = 0; j < 4; ++j) {
                    accG[i][j] += a[i] * bgr[j];
                    accU[i][j] += a[i] * bur[j];
                }
        }
        __syncthreads();
    }
#pragma unroll
    for (int im = 0; im < 4; ++im) {
        int m = m0 + ty * 4 + im;
        if (m < n) {
            float4 r;
            r.x = silu_f(accG[im][0]) * accU[im][0];
            r.y = silu_f(accG[im][1]) * accU[im][1];
            r.z = silu_f(accG[im][2]) * accU[im][2];
            r.w = silu_f(accG[im][3]) * accU[im][3];
            *(float4*)(out + (size_t)m * IDIM + n0 + tx * 4) = r;
        }
    }
}

// ---------------- down-proj GEMM: act[n,I] @ Wd[I,H] -> per-(t,k) slot ----------------
// grid (32, 16, 17)
__global__ __launch_bounds__(256) void gemm_down(
    const float* __restrict__ DownW, const float* __restrict__ SDownW)
{
    int ez = blockIdx.z;
    bool sh = (ez == NEXP);
    int n;
    const int* tok = nullptr;
    const int* kkl = nullptr;
    const float* Wd; const float* act;
    if (sh) { n = T_TOK; Wd = SDownW; act = g_act_s; }
    else {
        n = g_cnt[ez];
        tok = &g_tok[ez * T_TOK]; kkl = &g_kk[ez * T_TOK];
        Wd  = DownW + (size_t)ez * IDIM * HDIM;
        act = g_act + (size_t)g_off[ez] * IDIM;
    }
    int m0 = blockIdx.x * 64;
    if (m0 >= n) return;
    int n0 = blockIdx.y * 64;

    __shared__ float As[16][68];
    __shared__ float Bs[16][64];

    int tid = threadIdx.x;
    int tx = tid & 15, ty = tid >> 4;

    float acc[4][4];
#pragma unroll
    for (int i = 0; i < 4; ++i)
#pragma unroll
        for (int j = 0; j < 4; ++j) acc[i][j] = 0.f;

    int arow = tid >> 2, aquad = tid & 3;
    int brow = tid >> 4, bseg = tid & 15;

    int m_a = m0 + arow;
    const float* aptr = (m_a < n) ? (act + (size_t)m_a * IDIM) : nullptr;

    for (int k0 = 0; k0 < IDIM; k0 += 16) {
        float4 av = make_float4(0.f, 0.f, 0.f, 0.f);
        if (aptr) av = *(const float4*)(aptr + k0 + aquad * 4);
        As[aquad * 4 + 0][arow] = av.x;
        As[aquad * 4 + 1][arow] = av.y;
        As[aquad * 4 + 2][arow] = av.z;
        As[aquad * 4 + 3][arow] = av.w;
        {
            float4 b = *(const float4*)(Wd + (size_t)(k0 + brow) * HDIM + n0 + bseg * 4);
            *(float4*)&Bs[brow][bseg * 4] = b;
        }
        __syncthreads();
#pragma unroll
        for (int kk = 0; kk < 16; ++kk) {
            float4 a4 = *(const float4*)&As[kk][ty * 4];
            float4 b4 = *(const float4*)&Bs[kk][tx * 4];
            float a[4] = {a4.x, a4.y, a4.z, a4.w};
            float b[4] = {b4.x, b4.y, b4.z, b4.w};
#pragma unroll
            for (int i = 0; i < 4; ++i)
#pragma unroll
                for (int j = 0; j < 4; ++j)
                    acc[i][j] += a[i] * b[j];
        }
        __syncthreads();
    }
#pragma unroll
    for (int im = 0; im < 4; ++im) {
        int m = m0 + ty * 4 + im;
        if (m < n) {
            float* dst;
            if (sh) dst = g_part_s + (size_t)m * HDIM + n0 + tx * 4;
            else    dst = g_part + (size_t)(tok[m] * TOPK + kkl[m]) * HDIM + n0 + tx * 4;
            float4 r = make_float4(acc[im][0], acc[im][1], acc[im][2], acc[im][3]);
            *(float4*)dst = r;
        }
    }
}

// ---------------- deterministic combine (float4 vectorized) ----------------
__global__ void combine_kernel(float* __restrict__ out)
{
    int idx = blockIdx.x * 256 + threadIdx.x;   // over (T*H)/4 float4s
    int t  = idx >> 8;                          // H/4 = 256 float4s per token
    int h4 = idx & 255;

    const float4* ps = (const float4*)g_part_s;
    const float4* pp = (const float4*)g_part;

    float4 v = ps[idx];
#pragma unroll
    for (int k = 0; k < TOPK; ++k) {
        float4 p = pp[(size_t)(t * TOPK + k) * 256 + h4];
        v.x += p.x; v.y += p.y; v.z += p.z; v.w += p.w;
    }
    ((float4*)out)[idx] = v;
}

// ---------------- launch ----------------
extern "C" void kernel_launch(void* const* d_in, const int* in_sizes, int n_in,
                              void* d_out, int out_size)
{
    const float* X   = (const float*)d_in[0];   // [2,1024,1024]
    const float* RW  = (const float*)d_in[1];   // [1024,16]
    const float* GW  = (const float*)d_in[2];   // [16,1024,512]
    const float* UW  = (const float*)d_in[3];   // [16,1024,512]
    const float* DW  = (const float*)d_in[4];   // [16,512,1024]
    const float* SG  = (const float*)d_in[5];   // [1024,512]
    const float* SU  = (const float*)d_in[6];   // [1024,512]
    const float* SD  = (const float*)d_in[7];   // [512,1024]
    float* out = (float*)d_out;

    router_kernel<<<T_TOK / 8, 256>>>(X, RW);
    lists_kernel<<<NEXP, 256>>>();
    offsets_kernel<<<1, 32>>>();
    gemm_gu<<<dim3(T_TOK / 64, IDIM / 64, NEXP + 1), 256>>>(X, GW, UW, SG, SU);
    gemm_down<<<dim3(T_TOK / 64, HDIM / 64, NEXP + 1), 256>>>(DW, SD);
    combine_kernel<<<(T_TOK * HDIM) / (256 * 4), 256>>>(out);
}

// round 6
// speedup vs baseline: 1.6581x; 1.6581x over previous
#include <cuda_runtime.h>
#include <cuda_bf16.h>
#include <math.h>
#include <stdint.h>

#define T_TOK 2048
#define HDIM  1024
#define IDIM  512
#define NEXP  16
#define TOPK  4
#define RTOT  (T_TOK * TOPK)          // 8192 routed rows (exact)
#define ACT_ROWS (RTOT + T_TOK)       // + 2048 shared-expert rows = 10240

// ---------------- PTX helpers (sm_80+ only; no tcgen05/TMA) ----------------
__device__ __forceinline__ uint32_t smem_u32(const void* p) {
    uint32_t a;
    asm("{ .reg .u64 t; cvta.to.shared.u64 t, %1; cvt.u32.u64 %0, t; }" : "=r"(a) : "l"(p));
    return a;
}
#define CP_ASYNC16(sm, gp) \
    asm volatile("cp.async.cg.shared.global [%0], [%1], 16;" :: "r"(sm), "l"(gp) : "memory")
#define CP_COMMIT()  asm volatile("cp.async.commit_group;" ::: "memory")
#define CP_WAIT0()   asm volatile("cp.async.wait_group 0;" ::: "memory")
#define CP_WAIT1()   asm volatile("cp.async.wait_group 1;" ::: "memory")
#define LDSM_X4(r, a) \
    asm volatile("ldmatrix.sync.aligned.m8n8.x4.shared.b16 {%0,%1,%2,%3}, [%4];" \
        : "=r"((r)[0]), "=r"((r)[1]), "=r"((r)[2]), "=r"((r)[3]) : "r"(a))
#define MMA_BF16(d, a, b) \
    asm volatile("mma.sync.aligned.m16n8k16.row.col.f32.bf16.bf16.f32 " \
        "{%0,%1,%2,%3}, {%4,%5,%6,%7}, {%8,%9}, {%0,%1,%2,%3};" \
        : "+f"((d)[0]), "+f"((d)[1]), "+f"((d)[2]), "+f"((d)[3]) \
        : "r"((a)[0]), "r"((a)[1]), "r"((a)[2]), "r"((a)[3]), "r"((b)[0]), "r"((b)[1]))

// ---------------- scratch ----------------
__device__ int   g_cnt[NEXP];
__device__ int   g_off[NEXP];
__device__ int   g_tok[NEXP * T_TOK];
__device__ int   g_kk [NEXP * T_TOK];
__device__ float g_wgt[NEXP * T_TOK];
__device__ int   g_topk_idx[T_TOK * TOPK];
__device__ float g_topk_w [T_TOK * TOPK];
__device__ int   g_inv[RTOT];                 // (t,k) -> global act row
__device__ float g_rowwgt[ACT_ROWS];          // routing weight per act row (1 for shared)
__device__ __align__(16) __nv_bfloat16 g_xhi[(size_t)T_TOK * HDIM];
__device__ __align__(16) __nv_bfloat16 g_xlo[(size_t)T_TOK * HDIM];
__device__ __align__(16) __nv_bfloat16 g_tg_hi[(size_t)17 * IDIM * HDIM];
__device__ __align__(16) __nv_bfloat16 g_tg_lo[(size_t)17 * IDIM * HDIM];
__device__ __align__(16) __nv_bfloat16 g_tu_hi[(size_t)17 * IDIM * HDIM];
__device__ __align__(16) __nv_bfloat16 g_tu_lo[(size_t)17 * IDIM * HDIM];
__device__ __align__(16) __nv_bfloat16 g_td_hi[(size_t)17 * HDIM * IDIM];
__device__ __align__(16) __nv_bfloat16 g_td_lo[(size_t)17 * HDIM * IDIM];
__device__ __align__(16) __nv_bfloat16 g_acthi[(size_t)ACT_ROWS * IDIM];
__device__ __align__(16) __nv_bfloat16 g_actlo[(size_t)ACT_ROWS * IDIM];
__device__ __align__(16) float g_gbuf[(size_t)ACT_ROWS * IDIM];   // gate fp32
__device__ __align__(16) float g_ubuf[(size_t)ACT_ROWS * IDIM];   // up fp32
__device__ __align__(16) float g_dbuf[(size_t)ACT_ROWS * HDIM];   // down fp32

// ---------------- router: warp per token ----------------
__global__ void router_kernel(const float* __restrict__ X, const float* __restrict__ RW)
{
    int warp = threadIdx.x >> 5, lane = threadIdx.x & 31;
    int t = blockIdx.x * 8 + warp;
    const float4* X4 = (const float4*)X;
    const float4* RW4 = (const float4*)RW;
    float acc[NEXP];
#pragma unroll
    for (int e = 0; e < NEXP; ++e) acc[e] = 0.f;
#pragma unroll
    for (int it = 0; it < 8; ++it) {
        int h4 = lane + it * 32;
        float4 xv = X4[(size_t)t * 256 + h4];
        int h = h4 * 4;
#pragma unroll
        for (int j = 0; j < 4; ++j) {
            float xs = (j==0)?xv.x:(j==1)?xv.y:(j==2)?xv.z:xv.w;
            float rw[NEXP];
#pragma unroll
            for (int q = 0; q < 4; ++q) {
                float4 rv = RW4[(size_t)(h + j) * 4 + q];
                rw[q*4+0]=rv.x; rw[q*4+1]=rv.y; rw[q*4+2]=rv.z; rw[q*4+3]=rv.w;
            }
#pragma unroll
            for (int e = 0; e < NEXP; ++e) acc[e] += xs * rw[e];
        }
    }
#pragma unroll
    for (int e = 0; e < NEXP; ++e)
#pragma unroll
        for (int off = 16; off > 0; off >>= 1)
            acc[e] += __shfl_xor_sync(0xffffffffu, acc[e], off);
    if (lane == 0) {
        float v[NEXP]; bool used[NEXP];
#pragma unroll
        for (int e = 0; e < NEXP; ++e) { v[e] = 1.f/(1.f+expf(-acc[e])); used[e]=false; }
        for (int k = 0; k < TOPK; ++k) {
            int best=-1; float bv=-1e30f;
            for (int e = 0; e < NEXP; ++e) if (!used[e] && v[e] > bv) { bv=v[e]; best=e; }
            used[best]=true;
            g_topk_idx[t*TOPK+k]=best; g_topk_w[t*TOPK+k]=bv;
        }
    }
}

// ---------------- deterministic compaction ----------------
__global__ void lists_kernel()
{
    __shared__ int s[256];
    int e = blockIdx.x, tid = threadIdx.x, base = 0;
    for (int t0 = 0; t0 < T_TOK; t0 += 256) {
        int t = t0 + tid, kk = -1; float w = 0.f;
#pragma unroll
        for (int k = 0; k < TOPK; ++k)
            if (g_topk_idx[t*TOPK+k] == e) { kk = k; w = g_topk_w[t*TOPK+k]; }
        int flag = (kk >= 0);
        s[tid] = flag; __syncthreads();
        for (int off = 1; off < 256; off <<= 1) {
            int v = (tid >= off) ? s[tid-off] : 0; __syncthreads();
            s[tid] += v; __syncthreads();
        }
        if (flag) { int o = e*T_TOK + base + s[tid]-1; g_tok[o]=t; g_kk[o]=kk; g_wgt[o]=w; }
        base += s[255]; __syncthreads();
    }
    if (tid == 0) g_cnt[e] = base;
}

__global__ void offsets_kernel()
{
    if (threadIdx.x == 0) { int r = 0; for (int e = 0; e < NEXP; ++e) { g_off[e]=r; r+=g_cnt[e]; } }
}

// inverse map (t,k)->row and per-row weights
__global__ void invmap_kernel()
{
    int e = blockIdx.x, tid = threadIdx.x;
    if (e == NEXP) {
        for (int t = tid; t < T_TOK; t += 256) g_rowwgt[RTOT + t] = 1.f;
    } else {
        int n = g_cnt[e], o = g_off[e];
        for (int i = tid; i < n; i += 256) {
            int row = o + i;
            g_inv[g_tok[e*T_TOK+i] * TOPK + g_kk[e*T_TOK+i]] = row;
            g_rowwgt[row] = g_wgt[e*T_TOK+i];
        }
    }
}

// ---------------- split X into bf16 hi/lo ----------------
__global__ void split_x_kernel(const float* __restrict__ X)
{
    int i4 = blockIdx.x * 256 + threadIdx.x;
    float4 v = ((const float4*)X)[i4];
    float a[4] = {v.x, v.y, v.z, v.w};
    uint32_t ph[2], pl[2];
#pragma unroll
    for (int p = 0; p < 2; ++p) {
        __nv_bfloat16 h0 = __float2bfloat16(a[p*2]);
        __nv_bfloat16 h1 = __float2bfloat16(a[p*2+1]);
        __nv_bfloat16 l0 = __float2bfloat16(a[p*2]   - __bfloat162float(h0));
        __nv_bfloat16 l1 = __float2bfloat16(a[p*2+1] - __bfloat162float(h1));
        ph[p] = ((uint32_t)__bfloat16_as_ushort(h1)<<16) | __bfloat16_as_ushort(h0);
        pl[p] = ((uint32_t)__bfloat16_as_ushort(l1)<<16) | __bfloat16_as_ushort(l0);
    }
    ((uint2*)g_xhi)[i4] = make_uint2(ph[0], ph[1]);
    ((uint2*)g_xlo)[i4] = make_uint2(pl[0], pl[1]);
}

// ---------------- transpose + split weights: src[e][R][C] -> dst[e0+e][C][R] ----------------
__global__ void transpose_split(const float* __restrict__ src,
                                __nv_bfloat16* __restrict__ dhi, __nv_bfloat16* __restrict__ dlo,
                                int R, int C, int e0)
{
    __shared__ float tile[32][33];
    int e = blockIdx.z, c0 = blockIdx.x*32, r0 = blockIdx.y*32;
    const float* s = src + (size_t)e * R * C;
    int tx = threadIdx.x, ty = threadIdx.y;
#pragma unroll
    for (int j = 0; j < 4; ++j)
        tile[ty + j*8][tx] = s[(size_t)(r0 + ty + j*8)*C + c0 + tx];
    __syncthreads();
    size_t db = (size_t)(e0 + e) * C * R;
#pragma unroll
    for (int j = 0; j < 4; ++j) {
        float v = tile[tx][ty + j*8];
        __nv_bfloat16 h = __float2bfloat16(v);
        __nv_bfloat16 l = __float2bfloat16(v - __bfloat162float(h));
        size_t o = db + (size_t)(c0 + ty + j*8)*R + r0 + tx;
        dhi[o] = h; dlo[o] = l;
    }
}

// ---------------- generic 3-pass split GEMM: C[m][n] = A[m][:] . B[n][:] ----------------
// BM=128, BN=128, BK=64. 8 warps (2x4), warp tile 64x32. cp.async double buffer.
#define BUFSZ 65536
#define DSMEM (2 * BUFSZ)
extern __shared__ __align__(1024) char dsm[];

__global__ __launch_bounds__(256, 1) void gemm3(
    const __nv_bfloat16* __restrict__ Ah, const __nv_bfloat16* __restrict__ Al,
    const __nv_bfloat16* __restrict__ Bh, const __nv_bfloat16* __restrict__ Bl,
    float* __restrict__ C, int K, int N, int gather)
{
    int e = blockIdx.z;
    bool sh = (e == NEXP);
    int n = sh ? T_TOK : g_cnt[e];
    int m0 = blockIdx.x * 128;
    if (m0 >= n) return;
    int n0 = blockIdx.y * 128;
    int act0 = sh ? RTOT : g_off[e];
    const __nv_bfloat16* Bhe = Bh + (size_t)e * N * K;
    const __nv_bfloat16* Ble = Bl + (size_t)e * N * K;

    __shared__ int s_arow[128];
    int tid = threadIdx.x, wid = tid >> 5, lane = tid & 31;
    if (tid < 128) {
        int m = m0 + tid;
        int mc = (m < n) ? m : (n - 1);
        s_arow[tid] = gather ? (sh ? mc : g_tok[e * T_TOK + mc]) : (act0 + mc);
    }
    __syncthreads();

    uint32_t sb = smem_u32(dsm);
    int lr = tid >> 1;             // row 0..127 (A and B tiles)
    int lq0 = (tid & 1) * 4;       // quad base 0 or 4
    const __nv_bfloat16* arh = Ah + (size_t)s_arow[lr] * K;
    const __nv_bfloat16* arl = Al + (size_t)s_arow[lr] * K;
    const __nv_bfloat16* brh = Bhe + (size_t)(n0 + lr) * K;
    const __nv_bfloat16* brl = Ble + (size_t)(n0 + lr) * K;
    uint32_t swrow = (uint32_t)lr * 128;

    // issue one 64-wide K chunk into buffer (c&1)
    auto issue = [&](int c) {
        int k0 = c * 64;
        uint32_t bb = sb + (uint32_t)(c & 1) * BUFSZ + swrow;
#pragma unroll
        for (int j = 0; j < 4; ++j) {
            int q = lq0 + j;
            uint32_t so = bb + (uint32_t)((q ^ (lr & 7)) << 4);
            CP_ASYNC16(so,          arh + k0 + q * 8);
            CP_ASYNC16(so + 16384,  arl + k0 + q * 8);
            CP_ASYNC16(so + 32768,  brh + k0 + q * 8);
            CP_ASYNC16(so + 49152,  brl + k0 + q * 8);
        }
        CP_COMMIT();
    };

    float acc[4][4][4];
#pragma unroll
    for (int mt = 0; mt < 4; ++mt)
#pragma unroll
        for (int nt = 0; nt < 4; ++nt)
#pragma unroll
            for (int q = 0; q < 4; ++q) acc[mt][nt][q] = 0.f;

    int wr = wid >> 2, wc = wid & 3;           // 2 x 4 warp grid
    int NC = K / 64;

    issue(0);
    for (int c = 0; c < NC; ++c) {
        if (c + 1 < NC) { issue(c + 1); CP_WAIT1(); }
        else            { CP_WAIT0(); }
        __syncthreads();

        uint32_t bb  = sb + (uint32_t)(c & 1) * BUFSZ;
        uint32_t Ahb = bb, Alb = bb + 16384, Bhb = bb + 32768, Blb = bb + 49152;

#pragma unroll
        for (int ks = 0; ks < 4; ++ks) {
            uint32_t afh[4][4], afl[4][4], bfh[4][2], bfl[4][2];
            int ar = wr * 64 + (lane & 15);
            int aq = 2 * ks + (lane >> 4);
#pragma unroll
            for (int mt = 0; mt < 4; ++mt) {
                int r = ar + mt * 16;
                uint32_t off = (uint32_t)(r * 128 + ((aq ^ (r & 7)) << 4));
                LDSM_X4(afh[mt], Ahb + off);
                LDSM_X4(afl[mt], Alb + off);
            }
            int br0 = wc * 32 + ((lane >> 4) << 3) + (lane & 7);
            int bq  = 2 * ks + ((lane >> 3) & 1);
#pragma unroll
            for (int np = 0; np < 2; ++np) {
                int r = br0 + np * 16;
                uint32_t off = (uint32_t)(r * 128 + ((bq ^ (r & 7)) << 4));
                uint32_t t4[4];
                LDSM_X4(t4, Bhb + off);
                bfh[np*2][0]=t4[0]; bfh[np*2][1]=t4[1]; bfh[np*2+1][0]=t4[2]; bfh[np*2+1][1]=t4[3];
                LDSM_X4(t4, Blb + off);
                bfl[np*2][0]=t4[0]; bfl[np*2][1]=t4[1]; bfl[np*2+1][0]=t4[2]; bfl[np*2+1][1]=t4[3];
            }
#pragma unroll
            for (int mt = 0; mt < 4; ++mt)
#pragma unroll
                for (int nt = 0; nt < 4; ++nt) {
                    MMA_BF16(acc[mt][nt], afh[mt], bfh[nt]);
                    MMA_BF16(acc[mt][nt], afh[mt], bfl[nt]);
                    MMA_BF16(acc[mt][nt], afl[mt], bfh[nt]);
                }
        }
        __syncthreads();
    }

    // epilogue: write fp32 C rows act0+m (guard m<n)
#pragma unroll
    for (int mt = 0; mt < 4; ++mt) {
        int rbase = m0 + wr * 64 + mt * 16 + (lane >> 2);
#pragma unroll
        for (int half = 0; half < 2; ++half) {
            int m = rbase + half * 8;
            if (m < n) {
                float* cp = C + (size_t)(act0 + m) * N + n0 + wc * 32 + (lane & 3) * 2;
#pragma unroll
                for (int nt = 0; nt < 4; ++nt) {
                    float2 v = make_float2(acc[mt][nt][half*2], acc[mt][nt][half*2+1]);
                    *(float2*)(cp + nt * 8) = v;
                }
            }
        }
    }
}

// ---------------- silu(w.g)*(w.u) and split to bf16 hi/lo ----------------
__global__ void silu_split_kernel()
{
    int i4 = blockIdx.x * 256 + threadIdx.x;       // float4 index, 128 per row
    int row = i4 >> 7;
    float aw = g_rowwgt[row];
    float4 g = ((const float4*)g_gbuf)[i4];
    float4 u = ((const float4*)g_ubuf)[i4];
    float gg[4] = {g.x, g.y, g.z, g.w};
    float uu[4] = {u.x, u.y, u.z, u.w};
    uint32_t ph[2], pl[2];
#pragma unroll
    for (int p = 0; p < 2; ++p) {
        float a0, a1;
        {
            float gv = gg[p*2] * aw, uv = uu[p*2] * aw;
            a0 = (gv / (1.f + expf(-gv))) * uv;
            gv = gg[p*2+1] * aw; uv = uu[p*2+1] * aw;
            a1 = (gv / (1.f + expf(-gv))) * uv;
        }
        __nv_bfloat16 h0 = __float2bfloat16(a0), h1 = __float2bfloat16(a1);
        __nv_bfloat16 l0 = __float2bfloat16(a0 - __bfloat162float(h0));
        __nv_bfloat16 l1 = __float2bfloat16(a1 - __bfloat162float(h1));
        ph[p] = ((uint32_t)__bfloat16_as_ushort(h1)<<16) | __bfloat16_as_ushort(h0);
        pl[p] = ((uint32_t)__bfloat16_as_ushort(l1)<<16) | __bfloat16_as_ushort(l0);
    }
    ((uint2*)g_acthi)[i4] = make_uint2(ph[0], ph[1]);
    ((uint2*)g_actlo)[i4] = make_uint2(pl[0], pl[1]);
}

// ---------------- combine: out = shared row + sum_k routed rows ----------------
__global__ void combine_kernel(float* __restrict__ out)
{
    int idx = blockIdx.x * 256 + threadIdx.x;      // float4 over T*H
    int t = idx >> 8, h4 = idx & 255;
    const float4* db = (const float4*)g_dbuf;
    float4 v = db[(size_t)(RTOT + t) * 256 + h4];
#pragma unroll
    for (int k = 0; k < TOPK; ++k) {
        float4 p = db[(size_t)g_inv[t * TOPK + k] * 256 + h4];
        v.x += p.x; v.y += p.y; v.z += p.z; v.w += p.w;
    }
    ((float4*)out)[idx] = v;
}

// ---------------- launch ----------------
extern "C" void kernel_launch(void* const* d_in, const int* in_sizes, int n_in,
                              void* d_out, int out_size)
{
    const float* X  = (const float*)d_in[0];
    const float* RW = (const float*)d_in[1];
    const float* GW = (const float*)d_in[2];
    const float* UW = (const float*)d_in[3];
    const float* DW = (const float*)d_in[4];
    const float* SG = (const float*)d_in[5];
    const float* SU = (const float*)d_in[6];
    const float* SD = (const float*)d_in[7];
    float* out = (float*)d_out;

    cudaFuncSetAttribute(gemm3, cudaFuncAttributeMaxDynamicSharedMemorySize, DSMEM);

    __nv_bfloat16 *xhi, *xlo, *tgh, *tgl, *tuh, *tul, *tdh, *tdl, *ahi, *alo;
    float *gbuf, *ubuf, *dbuf;
    cudaGetSymbolAddress((void**)&xhi, g_xhi);  cudaGetSymbolAddress((void**)&xlo, g_xlo);
    cudaGetSymbolAddress((void**)&tgh, g_tg_hi); cudaGetSymbolAddress((void**)&tgl, g_tg_lo);
    cudaGetSymbolAddress((void**)&tuh, g_tu_hi); cudaGetSymbolAddress((void**)&tul, g_tu_lo);
    cudaGetSymbolAddress((void**)&tdh, g_td_hi); cudaGetSymbolAddress((void**)&tdl, g_td_lo);
    cudaGetSymbolAddress((void**)&ahi, g_acthi); cudaGetSymbolAddress((void**)&alo, g_actlo);
    cudaGetSymbolAddress((void**)&gbuf, g_gbuf); cudaGetSymbolAddress((void**)&ubuf, g_ubuf);
    cudaGetSymbolAddress((void**)&dbuf, g_dbuf);

    router_kernel<<<T_TOK / 8, 256>>>(X, RW);
    lists_kernel<<<NEXP, 256>>>();
    offsets_kernel<<<1, 32>>>();
    invmap_kernel<<<NEXP + 1, 256>>>();
    split_x_kernel<<<(T_TOK * HDIM) / (4 * 256), 256>>>(X);

    transpose_split<<<dim3(IDIM/32, HDIM/32, NEXP), dim3(32,8)>>>(GW, tgh, tgl, HDIM, IDIM, 0);
    transpose_split<<<dim3(IDIM/32, HDIM/32, NEXP), dim3(32,8)>>>(UW, tuh, tul, HDIM, IDIM, 0);
    transpose_split<<<dim3(IDIM/32, HDIM/32, 1),    dim3(32,8)>>>(SG, tgh, tgl, HDIM, IDIM, NEXP);
    transpose_split<<<dim3(IDIM/32, HDIM/32, 1),    dim3(32,8)>>>(SU, tuh, tul, HDIM, IDIM, NEXP);
    transpose_split<<<dim3(HDIM/32, IDIM/32, NEXP), dim3(32,8)>>>(DW, tdh, tdl, IDIM, HDIM, 0);
    transpose_split<<<dim3(HDIM/32, IDIM/32, 1),    dim3(32,8)>>>(SD, tdh, tdl, IDIM, HDIM, NEXP);

    // gate, up: A = X split (gathered), K=HDIM, N=IDIM
    gemm3<<<dim3(T_TOK/128, IDIM/128, NEXP+1), 256, DSMEM>>>(xhi, xlo, tgh, tgl, gbuf, HDIM, IDIM, 1);
    gemm3<<<dim3(T_TOK/128, IDIM/128, NEXP+1), 256, DSMEM>>>(xhi, xlo, tuh, tul, ubuf, HDIM, IDIM, 1);
    silu_split_kernel<<<(ACT_ROWS * IDIM) / (4 * 256), 256>>>();
    // down: A = act split (compact rows), K=IDIM, N=HDIM
    gemm3<<<dim3(T_TOK/128, HDIM/128, NEXP+1), 256, DSMEM>>>(ahi, alo, tdh, tdl, dbuf, IDIM, HDIM, 0);
    combine_kernel<<<(T_TOK * HDIM) / (256 * 4), 256>>>(out);
}

// round 7
// speedup vs baseline: 1.7951x; 1.0826x over previous
#include <cuda_runtime.h>
#include <cuda_bf16.h>
#include <math.h>
#include <stdint.h>

#define T_TOK 2048
#define HDIM  1024
#define IDIM  512
#define NEXP  16
#define TOPK  4
#define RTOT  (T_TOK * TOPK)          // 8192 routed rows (exact)
#define ACT_ROWS (RTOT + T_TOK)       // + 2048 shared-expert rows

// ---------------- PTX helpers (sm_80+ only) ----------------
__device__ __forceinline__ uint32_t smem_u32(const void* p) {
    uint32_t a;
    asm("{ .reg .u64 t; cvta.to.shared.u64 t, %1; cvt.u32.u64 %0, t; }" : "=r"(a) : "l"(p));
    return a;
}
#define CP_ASYNC16(sm, gp) \
    asm volatile("cp.async.cg.shared.global [%0], [%1], 16;" :: "r"(sm), "l"(gp) : "memory")
#define CP_COMMIT()  asm volatile("cp.async.commit_group;" ::: "memory")
#define CP_WAIT0()   asm volatile("cp.async.wait_group 0;" ::: "memory")
#define CP_WAIT1()   asm volatile("cp.async.wait_group 1;" ::: "memory")
#define LDSM_X4(r, a) \
    asm volatile("ldmatrix.sync.aligned.m8n8.x4.shared.b16 {%0,%1,%2,%3}, [%4];" \
        : "=r"((r)[0]), "=r"((r)[1]), "=r"((r)[2]), "=r"((r)[3]) : "r"(a))
#define MMA_BF16(d, a, b) \
    asm volatile("mma.sync.aligned.m16n8k16.row.col.f32.bf16.bf16.f32 " \
        "{%0,%1,%2,%3}, {%4,%5,%6,%7}, {%8,%9}, {%0,%1,%2,%3};" \
        : "+f"((d)[0]), "+f"((d)[1]), "+f"((d)[2]), "+f"((d)[3]) \
        : "r"((a)[0]), "r"((a)[1]), "r"((a)[2]), "r"((a)[3]), "r"((b)[0]), "r"((b)[1]))

// ---------------- scratch ----------------
__device__ int   g_cnt[NEXP];
__device__ int   g_off[NEXP];
__device__ int   g_tok[NEXP * T_TOK];
__device__ int   g_kk [NEXP * T_TOK];
__device__ float g_wgt[NEXP * T_TOK];
__device__ int   g_topk_idx[T_TOK * TOPK];
__device__ float g_topk_w [T_TOK * TOPK];
__device__ int   g_inv[RTOT];
__device__ float g_rowwgt[ACT_ROWS];
__device__ __align__(16) __nv_bfloat16 g_xhi[(size_t)T_TOK * HDIM];
__device__ __align__(16) __nv_bfloat16 g_xlo[(size_t)T_TOK * HDIM];
__device__ __align__(16) __nv_bfloat16 g_tg_hi[(size_t)17 * IDIM * HDIM];
__device__ __align__(16) __nv_bfloat16 g_tg_lo[(size_t)17 * IDIM * HDIM];
__device__ __align__(16) __nv_bfloat16 g_tu_hi[(size_t)17 * IDIM * HDIM];
__device__ __align__(16) __nv_bfloat16 g_tu_lo[(size_t)17 * IDIM * HDIM];
__device__ __align__(16) __nv_bfloat16 g_td_hi[(size_t)17 * HDIM * IDIM];
__device__ __align__(16) __nv_bfloat16 g_td_lo[(size_t)17 * HDIM * IDIM];
__device__ __align__(16) __nv_bfloat16 g_acthi[(size_t)ACT_ROWS * IDIM];
__device__ __align__(16) __nv_bfloat16 g_actlo[(size_t)ACT_ROWS * IDIM];
__device__ __align__(16) float g_dbuf[(size_t)ACT_ROWS * HDIM];

// ---------------- router: warp per token ----------------
__global__ void router_kernel(const float* __restrict__ X, const float* __restrict__ RW)
{
    int warp = threadIdx.x >> 5, lane = threadIdx.x & 31;
    int t = blockIdx.x * 8 + warp;
    const float4* X4 = (const float4*)X;
    const float4* RW4 = (const float4*)RW;
    float acc[NEXP];
#pragma unroll
    for (int e = 0; e < NEXP; ++e) acc[e] = 0.f;
#pragma unroll
    for (int it = 0; it < 8; ++it) {
        int h4 = lane + it * 32;
        float4 xv = X4[(size_t)t * 256 + h4];
        int h = h4 * 4;
#pragma unroll
        for (int j = 0; j < 4; ++j) {
            float xs = (j==0)?xv.x:(j==1)?xv.y:(j==2)?xv.z:xv.w;
            float rw[NEXP];
#pragma unroll
            for (int q = 0; q < 4; ++q) {
                float4 rv = RW4[(size_t)(h + j) * 4 + q];
                rw[q*4+0]=rv.x; rw[q*4+1]=rv.y; rw[q*4+2]=rv.z; rw[q*4+3]=rv.w;
            }
#pragma unroll
            for (int e = 0; e < NEXP; ++e) acc[e] += xs * rw[e];
        }
    }
#pragma unroll
    for (int e = 0; e < NEXP; ++e)
#pragma unroll
        for (int off = 16; off > 0; off >>= 1)
            acc[e] += __shfl_xor_sync(0xffffffffu, acc[e], off);
    if (lane == 0) {
        float v[NEXP]; bool used[NEXP];
#pragma unroll
        for (int e = 0; e < NEXP; ++e) { v[e] = 1.f/(1.f+expf(-acc[e])); used[e]=false; }
        for (int k = 0; k < TOPK; ++k) {
            int best=-1; float bv=-1e30f;
            for (int e = 0; e < NEXP; ++e) if (!used[e] && v[e] > bv) { bv=v[e]; best=e; }
            used[best]=true;
            g_topk_idx[t*TOPK+k]=best; g_topk_w[t*TOPK+k]=bv;
        }
    }
}

// ---------------- deterministic compaction ----------------
__global__ void lists_kernel()
{
    __shared__ int s[256];
    int e = blockIdx.x, tid = threadIdx.x, base = 0;
    for (int t0 = 0; t0 < T_TOK; t0 += 256) {
        int t = t0 + tid, kk = -1; float w = 0.f;
#pragma unroll
        for (int k = 0; k < TOPK; ++k)
            if (g_topk_idx[t*TOPK+k] == e) { kk = k; w = g_topk_w[t*TOPK+k]; }
        int flag = (kk >= 0);
        s[tid] = flag; __syncthreads();
        for (int off = 1; off < 256; off <<= 1) {
            int v = (tid >= off) ? s[tid-off] : 0; __syncthreads();
            s[tid] += v; __syncthreads();
        }
        if (flag) { int o = e*T_TOK + base + s[tid]-1; g_tok[o]=t; g_kk[o]=kk; g_wgt[o]=w; }
        base += s[255]; __syncthreads();
    }
    if (tid == 0) g_cnt[e] = base;
}

__global__ void offsets_kernel()
{
    if (threadIdx.x == 0) { int r = 0; for (int e = 0; e < NEXP; ++e) { g_off[e]=r; r+=g_cnt[e]; } }
}

__global__ void invmap_kernel()
{
    int e = blockIdx.x, tid = threadIdx.x;
    if (e == NEXP) {
        for (int t = tid; t < T_TOK; t += 256) g_rowwgt[RTOT + t] = 1.f;
    } else {
        int n = g_cnt[e], o = g_off[e];
        for (int i = tid; i < n; i += 256) {
            int row = o + i;
            g_inv[g_tok[e*T_TOK+i] * TOPK + g_kk[e*T_TOK+i]] = row;
            g_rowwgt[row] = g_wgt[e*T_TOK+i];
        }
    }
}

// ---------------- split X into bf16 hi/lo ----------------
__global__ void split_x_kernel(const float* __restrict__ X)
{
    int i4 = blockIdx.x * 256 + threadIdx.x;
    float4 v = ((const float4*)X)[i4];
    float a[4] = {v.x, v.y, v.z, v.w};
    uint32_t ph[2], pl[2];
#pragma unroll
    for (int p = 0; p < 2; ++p) {
        __nv_bfloat16 h0 = __float2bfloat16(a[p*2]);
        __nv_bfloat16 h1 = __float2bfloat16(a[p*2+1]);
        __nv_bfloat16 l0 = __float2bfloat16(a[p*2]   - __bfloat162float(h0));
        __nv_bfloat16 l1 = __float2bfloat16(a[p*2+1] - __bfloat162float(h1));
        ph[p] = ((uint32_t)__bfloat16_as_ushort(h1)<<16) | __bfloat16_as_ushort(h0);
        pl[p] = ((uint32_t)__bfloat16_as_ushort(l1)<<16) | __bfloat16_as_ushort(l0);
    }
    ((uint2*)g_xhi)[i4] = make_uint2(ph[0], ph[1]);
    ((uint2*)g_xlo)[i4] = make_uint2(pl[0], pl[1]);
}

// ---------------- transpose + split, vectorized: src[e][R][C] -> dst[e0+e][C][R] ----------------
// grid (C/32, R/128, E), block (32, 8)
__global__ void transpose_split(const float* __restrict__ src,
                                __nv_bfloat16* __restrict__ dhi, __nv_bfloat16* __restrict__ dlo,
                                int R, int C, int e0)
{
    __shared__ float tile[128][33];
    int e = blockIdx.z, c0 = blockIdx.x*32, r0 = blockIdx.y*128;
    const float* s = src + (size_t)e * R * C;
    int tx = threadIdx.x, ty = threadIdx.y;
#pragma unroll
    for (int j = 0; j < 16; ++j) {
        int r = ty + j*8;
        tile[r][tx] = s[(size_t)(r0 + r)*C + c0 + tx];
    }
    __syncthreads();
    size_t db = (size_t)(e0 + e) * C * R;
#pragma unroll
    for (int j = 0; j < 4; ++j) {
        int c = ty + j*8;
        float v0 = tile[4*tx+0][c], v1 = tile[4*tx+1][c];
        float v2 = tile[4*tx+2][c], v3 = tile[4*tx+3][c];
        __nv_bfloat16 h0 = __float2bfloat16(v0), h1 = __float2bfloat16(v1);
        __nv_bfloat16 h2 = __float2bfloat16(v2), h3 = __float2bfloat16(v3);
        __nv_bfloat16 l0 = __float2bfloat16(v0 - __bfloat162float(h0));
        __nv_bfloat16 l1 = __float2bfloat16(v1 - __bfloat162float(h1));
        __nv_bfloat16 l2 = __float2bfloat16(v2 - __bfloat162float(h2));
        __nv_bfloat16 l3 = __float2bfloat16(v3 - __bfloat162float(h3));
        uint2 hp = make_uint2(((uint32_t)__bfloat16_as_ushort(h1)<<16)|__bfloat16_as_ushort(h0),
                              ((uint32_t)__bfloat16_as_ushort(h3)<<16)|__bfloat16_as_ushort(h2));
        uint2 lp = make_uint2(((uint32_t)__bfloat16_as_ushort(l1)<<16)|__bfloat16_as_ushort(l0),
                              ((uint32_t)__bfloat16_as_ushort(l3)<<16)|__bfloat16_as_ushort(l2));
        size_t o = db + (size_t)(c0 + c)*R + r0 + 4*tx;
        *(uint2*)(dhi + o) = hp;
        *(uint2*)(dlo + o) = lp;
    }
}

// ---------------- fused gate+up GEMM + SiLU epilogue ----------------
// BM=128, BN=128 (gate and up both), BK=64. 512 threads, 4x4 warp grid, 32x32 warp tiles.
#define BUFGU 98304
#define DSMGU (2 * BUFGU)
extern __shared__ __align__(1024) char dsm[];

__global__ __launch_bounds__(512, 1) void gemm_gu3()
{
    int e = blockIdx.z;
    bool sh = (e == NEXP);
    int n = sh ? T_TOK : g_cnt[e];
    int m0 = blockIdx.x * 128;
    if (m0 >= n) return;
    int n0 = blockIdx.y * 128;
    int act0 = sh ? RTOT : g_off[e];
    int lbase = e * T_TOK;
    const int K = HDIM;

    __shared__ int s_arow[128];
    int tid = threadIdx.x, wid = tid >> 5, lane = tid & 31;
    if (tid < 128) {
        int m = m0 + tid;
        int mc = (m < n) ? m : (n - 1);
        s_arow[tid] = sh ? mc : g_tok[lbase + mc];
    }
    __syncthreads();

    uint32_t sb = smem_u32(dsm);
    // A loader mapping: 4 threads/row
    int lr = tid >> 2, aq0 = (tid & 3) * 2;
    const __nv_bfloat16* arh = g_xhi + (size_t)s_arow[lr] * K;
    const __nv_bfloat16* arl = g_xlo + (size_t)s_arow[lr] * K;
    // B loader mapping: 2 threads/row, gate (tid<256) / up (tid>=256)
    int br = (tid >> 1) & 127, bq0 = (tid & 1) * 4;
    int isUp = tid >> 8;
    size_t wrow = (size_t)(e * IDIM + n0 + br) * K;
    const __nv_bfloat16* bh = (isUp ? g_tu_hi : g_tg_hi) + wrow;
    const __nv_bfloat16* bl = (isUp ? g_tu_lo : g_tg_lo) + wrow;
    uint32_t boff = 32768u + (uint32_t)isUp * 32768u;

    auto issue = [&](int c) {
        int k0 = c * 64;
        uint32_t bb = sb + (uint32_t)(c & 1) * BUFGU;
        uint32_t abase = bb + (uint32_t)lr * 128;
#pragma unroll
        for (int j = 0; j < 2; ++j) {
            int q = aq0 + j;
            uint32_t so = abase + (uint32_t)((q ^ (lr & 7)) << 4);
            CP_ASYNC16(so,         arh + k0 + q * 8);
            CP_ASYNC16(so + 16384, arl + k0 + q * 8);
        }
        uint32_t bbase = bb + boff + (uint32_t)br * 128;
#pragma unroll
        for (int j = 0; j < 4; ++j) {
            int q = bq0 + j;
            uint32_t so = bbase + (uint32_t)((q ^ (br & 7)) << 4);
            CP_ASYNC16(so,         bh + k0 + q * 8);
            CP_ASYNC16(so + 16384, bl + k0 + q * 8);
        }
        CP_COMMIT();
    };

    float accG[2][4][4], accU[2][4][4];
#pragma unroll
    for (int mt = 0; mt < 2; ++mt)
#pragma unroll
        for (int nt = 0; nt < 4; ++nt)
#pragma unroll
            for (int q = 0; q < 4; ++q) { accG[mt][nt][q] = 0.f; accU[mt][nt][q] = 0.f; }

    int wr = wid >> 2, wc = wid & 3;          // 4x4 warp grid
    const int NC = K / 64;                    // 16

    issue(0);
    for (int c = 0; c < NC; ++c) {
        if (c + 1 < NC) { issue(c + 1); CP_WAIT1(); }
        else            { CP_WAIT0(); }
        __syncthreads();

        uint32_t bb  = sb + (uint32_t)(c & 1) * BUFGU;
        uint32_t Ahb = bb, Alb = bb + 16384;
        uint32_t Ghb = bb + 32768, Glb = bb + 49152;
        uint32_t Uhb = bb + 65536, Ulb = bb + 81920;

#pragma unroll
        for (int ks = 0; ks < 4; ++ks) {
            uint32_t afh[2][4], afl[2][4], bfh[4][2], bfl[4][2], t4[4];
            int ar = wr * 32 + (lane & 15);
            int aq = 2 * ks + (lane >> 4);
#pragma unroll
            for (int mt = 0; mt < 2; ++mt) {
                int r = ar + mt * 16;
                uint32_t off = (uint32_t)(r * 128 + ((aq ^ (r & 7)) << 4));
                LDSM_X4(afh[mt], Ahb + off);
                LDSM_X4(afl[mt], Alb + off);
            }
            int br0 = wc * 32 + ((lane >> 4) << 3) + (lane & 7);
            int bq  = 2 * ks + ((lane >> 3) & 1);
            // gate
#pragma unroll
            for (int np = 0; np < 2; ++np) {
                int r = br0 + np * 16;
                uint32_t off = (uint32_t)(r * 128 + ((bq ^ (r & 7)) << 4));
                LDSM_X4(t4, Ghb + off);
                bfh[np*2][0]=t4[0]; bfh[np*2][1]=t4[1]; bfh[np*2+1][0]=t4[2]; bfh[np*2+1][1]=t4[3];
                LDSM_X4(t4, Glb + off);
                bfl[np*2][0]=t4[0]; bfl[np*2][1]=t4[1]; bfl[np*2+1][0]=t4[2]; bfl[np*2+1][1]=t4[3];
            }
#pragma unroll
            for (int mt = 0; mt < 2; ++mt)
#pragma unroll
                for (int nt = 0; nt < 4; ++nt) {
                    MMA_BF16(accG[mt][nt], afh[mt], bfh[nt]);
                    MMA_BF16(accG[mt][nt], afh[mt], bfl[nt]);
                    MMA_BF16(accG[mt][nt], afl[mt], bfh[nt]);
                }
            // up (reuse b frag registers)
#pragma unroll
            for (int np = 0; np < 2; ++np) {
                int r = br0 + np * 16;
                uint32_t off = (uint32_t)(r * 128 + ((bq ^ (r & 7)) << 4));
                LDSM_X4(t4, Uhb + off);
                bfh[np*2][0]=t4[0]; bfh[np*2][1]=t4[1]; bfh[np*2+1][0]=t4[2]; bfh[np*2+1][1]=t4[3];
                LDSM_X4(t4, Ulb + off);
                bfl[np*2][0]=t4[0]; bfl[np*2][1]=t4[1]; bfl[np*2+1][0]=t4[2]; bfl[np*2+1][1]=t4[3];
            }
#pragma unroll
            for (int mt = 0; mt < 2; ++mt)
#pragma unroll
                for (int nt = 0; nt < 4; ++nt) {
                    MMA_BF16(accU[mt][nt], afh[mt], bfh[nt]);
                    MMA_BF16(accU[mt][nt], afh[mt], bfl[nt]);
                    MMA_BF16(accU[mt][nt], afl[mt], bfh[nt]);
                }
        }
        __syncthreads();
    }

    // epilogue: act = silu(aw*g) * (aw*u), split to bf16 hi/lo
#pragma unroll
    for (int mt = 0; mt < 2; ++mt) {
#pragma unroll
        for (int half = 0; half < 2; ++half) {
            int m = m0 + wr * 32 + mt * 16 + (lane >> 2) + half * 8;
            if (m < n) {
                float aw = sh ? 1.f : g_wgt[lbase + m];
                size_t rowb = (size_t)(act0 + m) * IDIM;
#pragma unroll
                for (int nt = 0; nt < 4; ++nt) {
                    int cc = n0 + wc * 32 + nt * 8 + (lane & 3) * 2;
                    float gv = accG[mt][nt][half*2]   * aw;
                    float uv = accU[mt][nt][half*2]   * aw;
                    float a0 = (gv / (1.f + expf(-gv))) * uv;
                    gv = accG[mt][nt][half*2+1] * aw;
                    uv = accU[mt][nt][half*2+1] * aw;
                    float a1 = (gv / (1.f + expf(-gv))) * uv;
                    __nv_bfloat16 h0 = __float2bfloat16(a0), h1 = __float2bfloat16(a1);
                    __nv_bfloat16 l0 = __float2bfloat16(a0 - __bfloat162float(h0));
                    __nv_bfloat16 l1 = __float2bfloat16(a1 - __bfloat162float(h1));
                    *(uint32_t*)(g_acthi + rowb + cc) =
                        ((uint32_t)__bfloat16_as_ushort(h1)<<16) | __bfloat16_as_ushort(h0);
                    *(uint32_t*)(g_actlo + rowb + cc) =
                        ((uint32_t)__bfloat16_as_ushort(l1)<<16) | __bfloat16_as_ushort(l0);
                }
            }
        }
    }
}

// ---------------- generic split GEMM (down proj) — unchanged from passing version ----------------
#define BUFSZ 65536
#define DSMEM (2 * BUFSZ)

__global__ __launch_bounds__(256, 1) void gemm3(
    const __nv_bfloat16* __restrict__ Ah, const __nv_bfloat16* __restrict__ Al,
    const __nv_bfloat16* __restrict__ Bh, const __nv_bfloat16* __restrict__ Bl,
    float* __restrict__ C, int K, int N, int gather)
{
    int e = blockIdx.z;
    bool sh = (e == NEXP);
    int n = sh ? T_TOK : g_cnt[e];
    int m0 = blockIdx.x * 128;
    if (m0 >= n) return;
    int n0 = blockIdx.y * 128;
    int act0 = sh ? RTOT : g_off[e];
    const __nv_bfloat16* Bhe = Bh + (size_t)e * N * K;
    const __nv_bfloat16* Ble = Bl + (size_t)e * N * K;

    __shared__ int s_arow[128];
    int tid = threadIdx.x, wid = tid >> 5, lane = tid & 31;
    if (tid < 128) {
        int m = m0 + tid;
        int mc = (m < n) ? m : (n - 1);
        s_arow[tid] = gather ? (sh ? mc : g_tok[e * T_TOK + mc]) : (act0 + mc);
    }
    __syncthreads();

    uint32_t sb = smem_u32(dsm);
    int lr = tid >> 1;
    int lq0 = (tid & 1) * 4;
    const __nv_bfloat16* arh = Ah + (size_t)s_arow[lr] * K;
    const __nv_bfloat16* arl = Al + (size_t)s_arow[lr] * K;
    const __nv_bfloat16* brh = Bhe + (size_t)(n0 + lr) * K;
    const __nv_bfloat16* brl = Ble + (size_t)(n0 + lr) * K;
    uint32_t swrow = (uint32_t)lr * 128;

    auto issue = [&](int c) {
        int k0 = c * 64;
        uint32_t bb = sb + (uint32_t)(c & 1) * BUFSZ + swrow;
#pragma unroll
        for (int j = 0; j < 4; ++j) {
            int q = lq0 + j;
            uint32_t so = bb + (uint32_t)((q ^ (lr & 7)) << 4);
            CP_ASYNC16(so,          arh + k0 + q * 8);
            CP_ASYNC16(so + 16384,  arl + k0 + q * 8);
            CP_ASYNC16(so + 32768,  brh + k0 + q * 8);
            CP_ASYNC16(so + 49152,  brl + k0 + q * 8);
        }
        CP_COMMIT();
    };

    float acc[4][4][4];
#pragma unroll
    for (int mt = 0; mt < 4; ++mt)
#pragma unroll
        for (int nt = 0; nt < 4; ++nt)
#pragma unroll
            for (int q = 0; q < 4; ++q) acc[mt][nt][q] = 0.f;

    int wr = wid >> 2, wc = wid & 3;
    int NC = K / 64;

    issue(0);
    for (int c = 0; c < NC; ++c) {
        if (c + 1 < NC) { issue(c + 1); CP_WAIT1(); }
        else            { CP_WAIT0(); }
        __syncthreads();

        uint32_t bb  = sb + (uint32_t)(c & 1) * BUFSZ;
        uint32_t Ahb = bb, Alb = bb + 16384, Bhb = bb + 32768, Blb = bb + 49152;

#pragma unroll
        for (int ks = 0; ks < 4; ++ks) {
            uint32_t afh[4][4], afl[4][4], bfh[4][2], bfl[4][2];
            int ar = wr * 64 + (lane & 15);
            int aq = 2 * ks + (lane >> 4);
#pragma unroll
            for (int mt = 0; mt < 4; ++mt) {
                int r = ar + mt * 16;
                uint32_t off = (uint32_t)(r * 128 + ((aq ^ (r & 7)) << 4));
                LDSM_X4(afh[mt], Ahb + off);
                LDSM_X4(afl[mt], Alb + off);
            }
            int br0 = wc * 32 + ((lane >> 4) << 3) + (lane & 7);
            int bq  = 2 * ks + ((lane >> 3) & 1);
#pragma unroll
            for (int np = 0; np < 2; ++np) {
                int r = br0 + np * 16;
                uint32_t off = (uint32_t)(r * 128 + ((bq ^ (r & 7)) << 4));
                uint32_t t4[4];
                LDSM_X4(t4, Bhb + off);
                bfh[np*2][0]=t4[0]; bfh[np*2][1]=t4[1]; bfh[np*2+1][0]=t4[2]; bfh[np*2+1][1]=t4[3];
                LDSM_X4(t4, Blb + off);
                bfl[np*2][0]=t4[0]; bfl[np*2][1]=t4[1]; bfl[np*2+1][0]=t4[2]; bfl[np*2+1][1]=t4[3];
            }
#pragma unroll
            for (int mt = 0; mt < 4; ++mt)
#pragma unroll
                for (int nt = 0; nt < 4; ++nt) {
                    MMA_BF16(acc[mt][nt], afh[mt], bfh[nt]);
                    MMA_BF16(acc[mt][nt], afh[mt], bfl[nt]);
                    MMA_BF16(acc[mt][nt], afl[mt], bfh[nt]);
                }
        }
        __syncthreads();
    }

#pragma unroll
    for (int mt = 0; mt < 4; ++mt) {
        int rbase = m0 + wr * 64 + mt * 16 + (lane >> 2);
#pragma unroll
        for (int half = 0; half < 2; ++half) {
            int m = rbase + half * 8;
            if (m < n) {
                float* cp = C + (size_t)(act0 + m) * N + n0 + wc * 32 + (lane & 3) * 2;
#pragma unroll
                for (int nt = 0; nt < 4; ++nt) {
                    float2 v = make_float2(acc[mt][nt][half*2], acc[mt][nt][half*2+1]);
                    *(float2*)(cp + nt * 8) = v;
                }
            }
        }
    }
}

// ---------------- combine ----------------
__global__ void combine_kernel(float* __restrict__ out)
{
    int idx = blockIdx.x * 256 + threadIdx.x;
    int t = idx >> 8, h4 = idx & 255;
    const float4* db = (const float4*)g_dbuf;
    float4 v = db[(size_t)(RTOT + t) * 256 + h4];
#pragma unroll
    for (int k = 0; k < TOPK; ++k) {
        float4 p = db[(size_t)g_inv[t * TOPK + k] * 256 + h4];
        v.x += p.x; v.y += p.y; v.z += p.z; v.w += p.w;
    }
    ((float4*)out)[idx] = v;
}

// ---------------- launch ----------------
extern "C" void kernel_launch(void* const* d_in, const int* in_sizes, int n_in,
                              void* d_out, int out_size)
{
    const float* X  = (const float*)d_in[0];
    const float* RW = (const float*)d_in[1];
    const float* GW = (const float*)d_in[2];
    const float* UW = (const float*)d_in[3];
    const float* DW = (const float*)d_in[4];
    const float* SG = (const float*)d_in[5];
    const float* SU = (const float*)d_in[6];
    const float* SD = (const float*)d_in[7];
    float* out = (float*)d_out;

    cudaFuncSetAttribute(gemm_gu3, cudaFuncAttributeMaxDynamicSharedMemorySize, DSMGU);
    cudaFuncSetAttribute(gemm3,    cudaFuncAttributeMaxDynamicSharedMemorySize, DSMEM);

    __nv_bfloat16 *tgh, *tgl, *tuh, *tul, *tdh, *tdl, *ahi, *alo;
    float *dbuf;
    cudaGetSymbolAddress((void**)&tgh, g_tg_hi); cudaGetSymbolAddress((void**)&tgl, g_tg_lo);
    cudaGetSymbolAddress((void**)&tuh, g_tu_hi); cudaGetSymbolAddress((void**)&tul, g_tu_lo);
    cudaGetSymbolAddress((void**)&tdh, g_td_hi); cudaGetSymbolAddress((void**)&tdl, g_td_lo);
    cudaGetSymbolAddress((void**)&ahi, g_acthi); cudaGetSymbolAddress((void**)&alo, g_actlo);
    cudaGetSymbolAddress((void**)&dbuf, g_dbuf);

    router_kernel<<<T_TOK / 8, 256>>>(X, RW);
    lists_kernel<<<NEXP, 256>>>();
    offsets_kernel<<<1, 32>>>();
    invmap_kernel<<<NEXP + 1, 256>>>();
    split_x_kernel<<<(T_TOK * HDIM) / (4 * 256), 256>>>(X);

    // gate/up: [E][H][I] -> [e][I][H]  (R=HDIM rows, C=IDIM cols)
    transpose_split<<<dim3(IDIM/32, HDIM/128, NEXP), dim3(32,8)>>>(GW, tgh, tgl, HDIM, IDIM, 0);
    transpose_split<<<dim3(IDIM/32, HDIM/128, NEXP), dim3(32,8)>>>(UW, tuh, tul, HDIM, IDIM, 0);
    transpose_split<<<dim3(IDIM/32, HDIM/128, 1),    dim3(32,8)>>>(SG, tgh, tgl, HDIM, IDIM, NEXP);
    transpose_split<<<dim3(IDIM/32, HDIM/128, 1),    dim3(32,8)>>>(SU, tuh, tul, HDIM, IDIM, NEXP);
    // down: [E][I][H] -> [e][H][I]  (R=IDIM rows, C=HDIM cols)
    transpose_split<<<dim3(HDIM/32, IDIM/128, NEXP), dim3(32,8)>>>(DW, tdh, tdl, IDIM, HDIM, 0);
    transpose_split<<<dim3(HDIM/32, IDIM/128, 1),    dim3(32,8)>>>(SD, tdh, tdl, IDIM, HDIM, NEXP);

    // fused gate+up + SiLU -> act hi/lo
    gemm_gu3<<<dim3(T_TOK/128, IDIM/128, NEXP+1), 512, DSMGU>>>();
    // down: act @ Dt -> dbuf
    gemm3<<<dim3(T_TOK/128, HDIM/128, NEXP+1), 256, DSMEM>>>(ahi, alo, tdh, tdl, dbuf, IDIM, HDIM, 0);
    combine_kernel<<<(T_TOK * HDIM) / (256 * 4), 256>>>(out);
}

// round 8
// speedup vs baseline: 2.3248x; 1.2951x over previous
#include <cuda_runtime.h>
#include <cuda_bf16.h>
#include <cuda_fp16.h>
#include <math.h>
#include <stdint.h>

#define T_TOK 2048
#define HDIM  1024
#define IDIM  512
#define NEXP  16
#define TOPK  4
#define RTOT  (T_TOK * TOPK)          // 8192 routed rows (exact)
#define ACT_ROWS (RTOT + T_TOK)       // + 2048 shared-expert rows

// ---------------- PTX helpers (sm_80+ only) ----------------
__device__ __forceinline__ uint32_t smem_u32(const void* p) {
    uint32_t a;
    asm("{ .reg .u64 t; cvta.to.shared.u64 t, %1; cvt.u32.u64 %0, t; }" : "=r"(a) : "l"(p));
    return a;
}
#define CP_ASYNC16(sm, gp) \
    asm volatile("cp.async.cg.shared.global [%0], [%1], 16;" :: "r"(sm), "l"(gp) : "memory")
#define CP_COMMIT()  asm volatile("cp.async.commit_group;" ::: "memory")
#define CP_WAIT0()   asm volatile("cp.async.wait_group 0;" ::: "memory")
#define CP_WAIT1()   asm volatile("cp.async.wait_group 1;" ::: "memory")
#define LDSM_X4(r, a) \
    asm volatile("ldmatrix.sync.aligned.m8n8.x4.shared.b16 {%0,%1,%2,%3}, [%4];" \
        : "=r"((r)[0]), "=r"((r)[1]), "=r"((r)[2]), "=r"((r)[3]) : "r"(a))
#define MMA_F16(d, a, b) \
    asm volatile("mma.sync.aligned.m16n8k16.row.col.f32.f16.f16.f32 " \
        "{%0,%1,%2,%3}, {%4,%5,%6,%7}, {%8,%9}, {%0,%1,%2,%3};" \
        : "+f"((d)[0]), "+f"((d)[1]), "+f"((d)[2]), "+f"((d)[3]) \
        : "r"((a)[0]), "r"((a)[1]), "r"((a)[2]), "r"((a)[3]), "r"((b)[0]), "r"((b)[1]))

// ---------------- scratch ----------------
__device__ int   g_cnt[NEXP];
__device__ int   g_off[NEXP];
__device__ int   g_tok[NEXP * T_TOK];
__device__ int   g_kk [NEXP * T_TOK];
__device__ float g_wgt[NEXP * T_TOK];
__device__ int   g_topk_idx[T_TOK * TOPK];
__device__ float g_topk_w [T_TOK * TOPK];
__device__ int   g_inv[RTOT];
__device__ __align__(16) __half g_xh  [(size_t)T_TOK * HDIM];
__device__ __align__(16) __half g_tg_hi[(size_t)17 * IDIM * HDIM];
__device__ __align__(16) __half g_tg_lo[(size_t)17 * IDIM * HDIM];
__device__ __align__(16) __half g_tu_hi[(size_t)17 * IDIM * HDIM];
__device__ __align__(16) __half g_tu_lo[(size_t)17 * IDIM * HDIM];
__device__ __align__(16) __half g_td_hi[(size_t)17 * HDIM * IDIM];
__device__ __align__(16) __half g_td_lo[(size_t)17 * HDIM * IDIM];
__device__ __align__(16) __half g_acth [(size_t)ACT_ROWS * IDIM];
__device__ __align__(16) float  g_dbuf [(size_t)ACT_ROWS * HDIM];

// ---------------- router: warp per token ----------------
__global__ void router_kernel(const float* __restrict__ X, const float* __restrict__ RW)
{
    int warp = threadIdx.x >> 5, lane = threadIdx.x & 31;
    int t = blockIdx.x * 8 + warp;
    const float4* X4 = (const float4*)X;
    const float4* RW4 = (const float4*)RW;
    float acc[NEXP];
#pragma unroll
    for (int e = 0; e < NEXP; ++e) acc[e] = 0.f;
#pragma unroll
    for (int it = 0; it < 8; ++it) {
        int h4 = lane + it * 32;
        float4 xv = X4[(size_t)t * 256 + h4];
        int h = h4 * 4;
#pragma unroll
        for (int j = 0; j < 4; ++j) {
            float xs = (j==0)?xv.x:(j==1)?xv.y:(j==2)?xv.z:xv.w;
            float rw[NEXP];
#pragma unroll
            for (int q = 0; q < 4; ++q) {
                float4 rv = RW4[(size_t)(h + j) * 4 + q];
                rw[q*4+0]=rv.x; rw[q*4+1]=rv.y; rw[q*4+2]=rv.z; rw[q*4+3]=rv.w;
            }
#pragma unroll
            for (int e = 0; e < NEXP; ++e) acc[e] += xs * rw[e];
        }
    }
#pragma unroll
    for (int e = 0; e < NEXP; ++e)
#pragma unroll
        for (int off = 16; off > 0; off >>= 1)
            acc[e] += __shfl_xor_sync(0xffffffffu, acc[e], off);
    if (lane == 0) {
        float v[NEXP]; bool used[NEXP];
#pragma unroll
        for (int e = 0; e < NEXP; ++e) { v[e] = 1.f/(1.f+expf(-acc[e])); used[e]=false; }
        for (int k = 0; k < TOPK; ++k) {
            int best=-1; float bv=-1e30f;
            for (int e = 0; e < NEXP; ++e) if (!used[e] && v[e] > bv) { bv=v[e]; best=e; }
            used[best]=true;
            g_topk_idx[t*TOPK+k]=best; g_topk_w[t*TOPK+k]=bv;
        }
    }
}

// ---------------- deterministic compaction ----------------
__global__ void lists_kernel()
{
    __shared__ int s[256];
    int e = blockIdx.x, tid = threadIdx.x, base = 0;
    for (int t0 = 0; t0 < T_TOK; t0 += 256) {
        int t = t0 + tid, kk = -1; float w = 0.f;
#pragma unroll
        for (int k = 0; k < TOPK; ++k)
            if (g_topk_idx[t*TOPK+k] == e) { kk = k; w = g_topk_w[t*TOPK+k]; }
        int flag = (kk >= 0);
        s[tid] = flag; __syncthreads();
        for (int off = 1; off < 256; off <<= 1) {
            int v = (tid >= off) ? s[tid-off] : 0; __syncthreads();
            s[tid] += v; __syncthreads();
        }
        if (flag) { int o = e*T_TOK + base + s[tid]-1; g_tok[o]=t; g_kk[o]=kk; g_wgt[o]=w; }
        base += s[255]; __syncthreads();
    }
    if (tid == 0) g_cnt[e] = base;
}

__global__ void offsets_kernel()
{
    if (threadIdx.x == 0) { int r = 0; for (int e = 0; e < NEXP; ++e) { g_off[e]=r; r+=g_cnt[e]; } }
}

__global__ void invmap_kernel()
{
    int e = blockIdx.x, tid = threadIdx.x;
    int n = g_cnt[e], o = g_off[e];
    for (int i = tid; i < n; i += 256)
        g_inv[g_tok[e*T_TOK+i] * TOPK + g_kk[e*T_TOK+i]] = o + i;
}

// ---------------- convert X to fp16 ----------------
__global__ void convert_x_kernel(const float* __restrict__ X)
{
    int i4 = blockIdx.x * 256 + threadIdx.x;
    float4 v = ((const float4*)X)[i4];
    __half h0 = __float2half(v.x), h1 = __float2half(v.y);
    __half h2 = __float2half(v.z), h3 = __float2half(v.w);
    uint2 p;
    p.x = ((uint32_t)__half_as_ushort(h1) << 16) | __half_as_ushort(h0);
    p.y = ((uint32_t)__half_as_ushort(h3) << 16) | __half_as_ushort(h2);
    ((uint2*)g_xh)[i4] = p;
}

// ---------------- transpose + split weights (fp16 hi/lo): src[e][R][C] -> dst[e0+e][C][R] ----------------
// grid (C/32, R/128, E), block (32, 8)
__global__ void transpose_split(const float* __restrict__ src,
                                __half* __restrict__ dhi, __half* __restrict__ dlo,
                                int R, int C, int e0)
{
    __shared__ float tile[128][33];
    int e = blockIdx.z, c0 = blockIdx.x*32, r0 = blockIdx.y*128;
    const float* s = src + (size_t)e * R * C;
    int tx = threadIdx.x, ty = threadIdx.y;
#pragma unroll
    for (int j = 0; j < 16; ++j) {
        int r = ty + j*8;
        tile[r][tx] = s[(size_t)(r0 + r)*C + c0 + tx];
    }
    __syncthreads();
    size_t db = (size_t)(e0 + e) * C * R;
#pragma unroll
    for (int j = 0; j < 4; ++j) {
        int c = ty + j*8;
        float v0 = tile[4*tx+0][c], v1 = tile[4*tx+1][c];
        float v2 = tile[4*tx+2][c], v3 = tile[4*tx+3][c];
        __half h0 = __float2half(v0), h1 = __float2half(v1);
        __half h2 = __float2half(v2), h3 = __float2half(v3);
        __half l0 = __float2half(v0 - __half2float(h0));
        __half l1 = __float2half(v1 - __half2float(h1));
        __half l2 = __float2half(v2 - __half2float(h2));
        __half l3 = __float2half(v3 - __half2float(h3));
        uint2 hp, lp;
        hp.x = ((uint32_t)__half_as_ushort(h1)<<16)|__half_as_ushort(h0);
        hp.y = ((uint32_t)__half_as_ushort(h3)<<16)|__half_as_ushort(h2);
        lp.x = ((uint32_t)__half_as_ushort(l1)<<16)|__half_as_ushort(l0);
        lp.y = ((uint32_t)__half_as_ushort(l3)<<16)|__half_as_ushort(l2);
        size_t o = db + (size_t)(c0 + c)*R + r0 + 4*tx;
        *(uint2*)(dhi + o) = hp;
        *(uint2*)(dlo + o) = lp;
    }
}

// ---------------- fused gate+up GEMM + SiLU epilogue (fp16 2-term split) ----------------
// BM=128, BN=128 both gate & up, BK=64. 512 threads, 4x4 warp grid, 32x32 warp tiles.
// Stage: A 16KB + Ghi 16 + Glo 16 + Uhi 16 + Ulo 16 = 80KB, double buffered.
#define BUFGU 81920
#define DSMGU (2 * BUFGU)
extern __shared__ __align__(1024) char dsm[];

__global__ __launch_bounds__(512, 1) void gemm_gu3()
{
    int e = blockIdx.z;
    bool sh = (e == NEXP);
    int n = sh ? T_TOK : g_cnt[e];
    int m0 = blockIdx.x * 128;
    if (m0 >= n) return;
    int n0 = blockIdx.y * 128;
    int act0 = sh ? RTOT : g_off[e];
    int lbase = e * T_TOK;
    const int K = HDIM;

    __shared__ int s_arow[128];
    int tid = threadIdx.x, wid = tid >> 5, lane = tid & 31;
    if (tid < 128) {
        int m = m0 + tid;
        int mc = (m < n) ? m : (n - 1);
        s_arow[tid] = sh ? mc : g_tok[lbase + mc];
    }
    __syncthreads();

    uint32_t sb = smem_u32(dsm);
    // A loader: 4 threads/row, 2 quads each (hi only)
    int lr = tid >> 2, aq0 = (tid & 3) * 2;
    const __half* arh = g_xh + (size_t)s_arow[lr] * K;
    // B loader: 2 threads/row; gate (tid<256) / up (tid>=256); 4 quads hi + 4 lo
    int br = (tid >> 1) & 127, bq0 = (tid & 1) * 4;
    int isUp = tid >> 8;
    size_t wrow = (size_t)(e * IDIM + n0 + br) * K;
    const __half* bh = (isUp ? g_tu_hi : g_tg_hi) + wrow;
    const __half* bl = (isUp ? g_tu_lo : g_tg_lo) + wrow;
    uint32_t boff = 16384u + (uint32_t)isUp * 32768u;

    auto issue = [&](int c) {
        int k0 = c * 64;
        uint32_t bb = sb + (uint32_t)(c & 1) * BUFGU;
        uint32_t abase = bb + (uint32_t)lr * 128;
#pragma unroll
        for (int j = 0; j < 2; ++j) {
            int q = aq0 + j;
            CP_ASYNC16(abase + (uint32_t)((q ^ (lr & 7)) << 4), arh + k0 + q * 8);
        }
        uint32_t bbase = bb + boff + (uint32_t)br * 128;
#pragma unroll
        for (int j = 0; j < 4; ++j) {
            int q = bq0 + j;
            uint32_t so = bbase + (uint32_t)((q ^ (br & 7)) << 4);
            CP_ASYNC16(so,         bh + k0 + q * 8);
            CP_ASYNC16(so + 16384, bl + k0 + q * 8);
        }
        CP_COMMIT();
    };

    float accG[2][4][4], accU[2][4][4];
#pragma unroll
    for (int mt = 0; mt < 2; ++mt)
#pragma unroll
        for (int nt = 0; nt < 4; ++nt)
#pragma unroll
            for (int q = 0; q < 4; ++q) { accG[mt][nt][q] = 0.f; accU[mt][nt][q] = 0.f; }

    int wr = wid >> 2, wc = wid & 3;          // 4x4 warp grid
    const int NC = K / 64;                    // 16

    issue(0);
    for (int c = 0; c < NC; ++c) {
        if (c + 1 < NC) { issue(c + 1); CP_WAIT1(); }
        else            { CP_WAIT0(); }
        __syncthreads();

        uint32_t bb  = sb + (uint32_t)(c & 1) * BUFGU;
        uint32_t Ahb = bb;
        uint32_t Ghb = bb + 16384, Glb = bb + 32768;
        uint32_t Uhb = bb + 49152, Ulb = bb + 65536;

#pragma unroll
        for (int ks = 0; ks < 4; ++ks) {
            uint32_t afh[2][4], bfh[4][2], bfl[4][2], t4[4];
            int ar = wr * 32 + (lane & 15);
            int aq = 2 * ks + (lane >> 4);
#pragma unroll
            for (int mt = 0; mt < 2; ++mt) {
                int r = ar + mt * 16;
                LDSM_X4(afh[mt], Ahb + (uint32_t)(r * 128 + ((aq ^ (r & 7)) << 4)));
            }
            int br0 = wc * 32 + ((lane >> 4) << 3) + (lane & 7);
            int bq  = 2 * ks + ((lane >> 3) & 1);
            // gate hi/lo
#pragma unroll
            for (int np = 0; np < 2; ++np) {
                int r = br0 + np * 16;
                uint32_t off = (uint32_t)(r * 128 + ((bq ^ (r & 7)) << 4));
                LDSM_X4(t4, Ghb + off);
                bfh[np*2][0]=t4[0]; bfh[np*2][1]=t4[1]; bfh[np*2+1][0]=t4[2]; bfh[np*2+1][1]=t4[3];
                LDSM_X4(t4, Glb + off);
                bfl[np*2][0]=t4[0]; bfl[np*2][1]=t4[1]; bfl[np*2+1][0]=t4[2]; bfl[np*2+1][1]=t4[3];
            }
#pragma unroll
            for (int mt = 0; mt < 2; ++mt)
#pragma unroll
                for (int nt = 0; nt < 4; ++nt) {
                    MMA_F16(accG[mt][nt], afh[mt], bfh[nt]);
                    MMA_F16(accG[mt][nt], afh[mt], bfl[nt]);
                }
            // up hi/lo (reuse frag regs)
#pragma unroll
            for (int np = 0; np < 2; ++np) {
                int r = br0 + np * 16;
                uint32_t off = (uint32_t)(r * 128 + ((bq ^ (r & 7)) << 4));
                LDSM_X4(t4, Uhb + off);
                bfh[np*2][0]=t4[0]; bfh[np*2][1]=t4[1]; bfh[np*2+1][0]=t4[2]; bfh[np*2+1][1]=t4[3];
                LDSM_X4(t4, Ulb + off);
                bfl[np*2][0]=t4[0]; bfl[np*2][1]=t4[1]; bfl[np*2+1][0]=t4[2]; bfl[np*2+1][1]=t4[3];
            }
#pragma unroll
            for (int mt = 0; mt < 2; ++mt)
#pragma unroll
                for (int nt = 0; nt < 4; ++nt) {
                    MMA_F16(accU[mt][nt], afh[mt], bfh[nt]);
                    MMA_F16(accU[mt][nt], afh[mt], bfl[nt]);
                }
        }
        __syncthreads();
    }

    // epilogue: act = silu(aw*g) * (aw*u) -> fp16
#pragma unroll
    for (int mt = 0; mt < 2; ++mt) {
#pragma unroll
        for (int half = 0; half < 2; ++half) {
            int m = m0 + wr * 32 + mt * 16 + (lane >> 2) + half * 8;
            if (m < n) {
                float aw = sh ? 1.f : g_wgt[lbase + m];
                size_t rowb = (size_t)(act0 + m) * IDIM;
#pragma unroll
                for (int nt = 0; nt < 4; ++nt) {
                    int cc = n0 + wc * 32 + nt * 8 + (lane & 3) * 2;
                    float gv = accG[mt][nt][half*2]   * aw;
                    float uv = accU[mt][nt][half*2]   * aw;
                    float a0 = (gv / (1.f + expf(-gv))) * uv;
                    gv = accG[mt][nt][half*2+1] * aw;
                    uv = accU[mt][nt][half*2+1] * aw;
                    float a1 = (gv / (1.f + expf(-gv))) * uv;
                    __half h0 = __float2half(a0), h1 = __float2half(a1);
                    *(uint32_t*)(g_acth + rowb + cc) =
                        ((uint32_t)__half_as_ushort(h1)<<16) | __half_as_ushort(h0);
                }
            }
        }
    }
}

// ---------------- down GEMM (fp16 2-term split), 2 CTAs/SM ----------------
// Stage: A 16KB + Bhi 16 + Blo 16 = 48KB, double buffered = 96KB.
#define BUFSZ 49152
#define DSMEM (2 * BUFSZ)

__global__ __launch_bounds__(256, 2) void gemm3(
    const __half* __restrict__ Ah,
    const __half* __restrict__ Bh, const __half* __restrict__ Bl,
    float* __restrict__ C, int K, int N)
{
    int e = blockIdx.z;
    bool sh = (e == NEXP);
    int n = sh ? T_TOK : g_cnt[e];
    int m0 = blockIdx.x * 128;
    if (m0 >= n) return;
    int n0 = blockIdx.y * 128;
    int act0 = sh ? RTOT : g_off[e];
    const __half* Bhe = Bh + (size_t)e * N * K;
    const __half* Ble = Bl + (size_t)e * N * K;

    int tid = threadIdx.x, wid = tid >> 5, lane = tid & 31;
    uint32_t sb = smem_u32(dsm);
    int lr = tid >> 1;
    int lq0 = (tid & 1) * 4;
    int mc = (m0 + lr < n) ? (m0 + lr) : (n - 1);
    const __half* arh = Ah + (size_t)(act0 + mc) * K;
    const __half* brh = Bhe + (size_t)(n0 + lr) * K;
    const __half* brl = Ble + (size_t)(n0 + lr) * K;
    uint32_t swrow = (uint32_t)lr * 128;

    auto issue = [&](int c) {
        int k0 = c * 64;
        uint32_t bb = sb + (uint32_t)(c & 1) * BUFSZ + swrow;
#pragma unroll
        for (int j = 0; j < 4; ++j) {
            int q = lq0 + j;
            uint32_t so = bb + (uint32_t)((q ^ (lr & 7)) << 4);
            CP_ASYNC16(so,          arh + k0 + q * 8);
            CP_ASYNC16(so + 16384,  brh + k0 + q * 8);
            CP_ASYNC16(so + 32768,  brl + k0 + q * 8);
        }
        CP_COMMIT();
    };

    float acc[4][4][4];
#pragma unroll
    for (int mt = 0; mt < 4; ++mt)
#pragma unroll
        for (int nt = 0; nt < 4; ++nt)
#pragma unroll
            for (int q = 0; q < 4; ++q) acc[mt][nt][q] = 0.f;

    int wr = wid >> 2, wc = wid & 3;
    int NC = K / 64;

    issue(0);
    for (int c = 0; c < NC; ++c) {
        if (c + 1 < NC) { issue(c + 1); CP_WAIT1(); }
        else            { CP_WAIT0(); }
        __syncthreads();

        uint32_t bb  = sb + (uint32_t)(c & 1) * BUFSZ;
        uint32_t Ahb = bb, Bhb = bb + 16384, Blb = bb + 32768;

#pragma unroll
        for (int ks = 0; ks < 4; ++ks) {
            uint32_t afh[4][4], bfh[4][2], bfl[4][2], t4[4];
            int ar = wr * 64 + (lane & 15);
            int aq = 2 * ks + (lane >> 4);
#pragma unroll
            for (int mt = 0; mt < 4; ++mt) {
                int r = ar + mt * 16;
                LDSM_X4(afh[mt], Ahb + (uint32_t)(r * 128 + ((aq ^ (r & 7)) << 4)));
            }
            int br0 = wc * 32 + ((lane >> 4) << 3) + (lane & 7);
            int bq  = 2 * ks + ((lane >> 3) & 1);
#pragma unroll
            for (int np = 0; np < 2; ++np) {
                int r = br0 + np * 16;
                uint32_t off = (uint32_t)(r * 128 + ((bq ^ (r & 7)) << 4));
                LDSM_X4(t4, Bhb + off);
                bfh[np*2][0]=t4[0]; bfh[np*2][1]=t4[1]; bfh[np*2+1][0]=t4[2]; bfh[np*2+1][1]=t4[3];
                LDSM_X4(t4, Blb + off);
                bfl[np*2][0]=t4[0]; bfl[np*2][1]=t4[1]; bfl[np*2+1][0]=t4[2]; bfl[np*2+1][1]=t4[3];
            }
#pragma unroll
            for (int mt = 0; mt < 4; ++mt)
#pragma unroll
                for (int nt = 0; nt < 4; ++nt) {
                    MMA_F16(acc[mt][nt], afh[mt], bfh[nt]);
                    MMA_F16(acc[mt][nt], afh[mt], bfl[nt]);
                }
        }
        __syncthreads();
    }

#pragma unroll
    for (int mt = 0; mt < 4; ++mt) {
        int rbase = m0 + wr * 64 + mt * 16 + (lane >> 2);
#pragma unroll
        for (int half = 0; half < 2; ++half) {
            int m = rbase + half * 8;
            if (m < n) {
                float* cp = C + (size_t)(act0 + m) * N + n0 + wc * 32 + (lane & 3) * 2;
#pragma unroll
                for (int nt = 0; nt < 4; ++nt) {
                    float2 v = make_float2(acc[mt][nt][half*2], acc[mt][nt][half*2+1]);
                    *(float2*)(cp + nt * 8) = v;
                }
            }
        }
    }
}

// ---------------- combine ----------------
__global__ void combine_kernel(float* __restrict__ out)
{
    int idx = blockIdx.x * 256 + threadIdx.x;
    int t = idx >> 8, h4 = idx & 255;
    const float4* db = (const float4*)g_dbuf;
    float4 v = db[(size_t)(RTOT + t) * 256 + h4];
#pragma unroll
    for (int k = 0; k < TOPK; ++k) {
        float4 p = db[(size_t)g_inv[t * TOPK + k] * 256 + h4];
        v.x += p.x; v.y += p.y; v.z += p.z; v.w += p.w;
    }
    ((float4*)out)[idx] = v;
}

// ---------------- launch ----------------
extern "C" void kernel_launch(void* const* d_in, const int* in_sizes, int n_in,
                              void* d_out, int out_size)
{
    const float* X  = (const float*)d_in[0];
    const float* RW = (const float*)d_in[1];
    const float* GW = (const float*)d_in[2];
    const float* UW = (const float*)d_in[3];
    const float* DW = (const float*)d_in[4];
    const float* SG = (const float*)d_in[5];
    const float* SU = (const float*)d_in[6];
    const float* SD = (const float*)d_in[7];
    float* out = (float*)d_out;

    cudaFuncSetAttribute(gemm_gu3, cudaFuncAttributeMaxDynamicSharedMemorySize, DSMGU);
    cudaFuncSetAttribute(gemm3,    cudaFuncAttributeMaxDynamicSharedMemorySize, DSMEM);

    __half *tgh, *tgl, *tuh, *tul, *tdh, *tdl, *ah;
    float *dbuf;
    cudaGetSymbolAddress((void**)&tgh, g_tg_hi); cudaGetSymbolAddress((void**)&tgl, g_tg_lo);
    cudaGetSymbolAddress((void**)&tuh, g_tu_hi); cudaGetSymbolAddress((void**)&tul, g_tu_lo);
    cudaGetSymbolAddress((void**)&tdh, g_td_hi); cudaGetSymbolAddress((void**)&tdl, g_td_lo);
    cudaGetSymbolAddress((void**)&ah,  g_acth);
    cudaGetSymbolAddress((void**)&dbuf, g_dbuf);

    router_kernel<<<T_TOK / 8, 256>>>(X, RW);
    lists_kernel<<<NEXP, 256>>>();
    offsets_kernel<<<1, 32>>>();
    invmap_kernel<<<NEXP, 256>>>();
    convert_x_kernel<<<(T_TOK * HDIM) / (4 * 256), 256>>>(X);

    // gate/up: [E][H][I] -> [e][I][H]
    transpose_split<<<dim3(IDIM/32, HDIM/128, NEXP), dim3(32,8)>>>(GW, tgh, tgl, HDIM, IDIM, 0);
    transpose_split<<<dim3(IDIM/32, HDIM/128, NEXP), dim3(32,8)>>>(UW, tuh, tul, HDIM, IDIM, 0);
    transpose_split<<<dim3(IDIM/32, HDIM/128, 1),    dim3(32,8)>>>(SG, tgh, tgl, HDIM, IDIM, NEXP);
    transpose_split<<<dim3(IDIM/32, HDIM/128, 1),    dim3(32,8)>>>(SU, tuh, tul, HDIM, IDIM, NEXP);
    // down: [E][I][H] -> [e][H][I]
    transpose_split<<<dim3(HDIM/32, IDIM/128, NEXP), dim3(32,8)>>>(DW, tdh, tdl, IDIM, HDIM, 0);
    transpose_split<<<dim3(HDIM/32, IDIM/128, 1),    dim3(32,8)>>>(SD, tdh, tdl, IDIM, HDIM, NEXP);

    // fused gate+up + SiLU -> act fp16
    gemm_gu3<<<dim3(T_TOK/128, IDIM/128, NEXP+1), 512, DSMGU>>>();
    // down: act @ Dt -> dbuf
    gemm3<<<dim3(T_TOK/128, HDIM/128, NEXP+1), 256, DSMEM>>>(ah, tdh, tdl, dbuf, IDIM, HDIM);
    combine_kernel<<<(T_TOK * HDIM) / (256 * 4), 256>>>(out);
}

// round 10
// speedup vs baseline: 3.2684x; 1.4058x over previous
#include <cuda_runtime.h>
#include <cuda_bf16.h>
#include <cuda_fp16.h>
#include <math.h>
#include <stdint.h>

#define T_TOK 2048
#define HDIM  1024
#define IDIM  512
#define NEXP  16
#define TOPK  4
#define RTOT  (T_TOK * TOPK)          // 8192 routed rows (exact)
#define ACT_ROWS (RTOT + T_TOK)       // + 2048 shared-expert rows

// ---------------- PTX helpers (sm_80+ only) ----------------
__device__ __forceinline__ uint32_t smem_u32(const void* p) {
    uint32_t a;
    asm("{ .reg .u64 t; cvta.to.shared.u64 t, %1; cvt.u32.u64 %0, t; }" : "=r"(a) : "l"(p));
    return a;
}
#define CP_ASYNC16(sm, gp) \
    asm volatile("cp.async.cg.shared.global [%0], [%1], 16;" :: "r"(sm), "l"(gp) : "memory")
#define CP_COMMIT()  asm volatile("cp.async.commit_group;" ::: "memory")
#define CP_WAIT0()   asm volatile("cp.async.wait_group 0;" ::: "memory")
#define CP_WAIT1()   asm volatile("cp.async.wait_group 1;" ::: "memory")
#define LDSM_X4(r, a) \
    asm volatile("ldmatrix.sync.aligned.m8n8.x4.shared.b16 {%0,%1,%2,%3}, [%4];" \
        : "=r"((r)[0]), "=r"((r)[1]), "=r"((r)[2]), "=r"((r)[3]) : "r"(a))
#define MMA_F16(d, a, b) \
    asm volatile("mma.sync.aligned.m16n8k16.row.col.f32.f16.f16.f32 " \
        "{%0,%1,%2,%3}, {%4,%5,%6,%7}, {%8,%9}, {%0,%1,%2,%3};" \
        : "+f"((d)[0]), "+f"((d)[1]), "+f"((d)[2]), "+f"((d)[3]) \
        : "r"((a)[0]), "r"((a)[1]), "r"((a)[2]), "r"((a)[3]), "r"((b)[0]), "r"((b)[1]))

// ---------------- scratch ----------------
__device__ int   g_cnt[NEXP];
__device__ int   g_off[NEXP];
__device__ int   g_tok[NEXP * T_TOK];
__device__ int   g_kk [NEXP * T_TOK];
__device__ float g_wgt[NEXP * T_TOK];
__device__ int   g_topk_idx[T_TOK * TOPK];
__device__ float g_topk_w [T_TOK * TOPK];
__device__ int   g_inv[RTOT];
__device__ __align__(16) __half g_xh  [(size_t)T_TOK * HDIM];
__device__ __align__(16) __half g_tg  [(size_t)17 * IDIM * HDIM];
__device__ __align__(16) __half g_tu  [(size_t)17 * IDIM * HDIM];
__device__ __align__(16) __half g_td  [(size_t)17 * HDIM * IDIM];
__device__ __align__(16) __half g_acth[(size_t)ACT_ROWS * IDIM];
__device__ __align__(16) float  g_dbuf[(size_t)ACT_ROWS * HDIM];

// ---------------- router: warp per token ----------------
__global__ void router_kernel(const float* __restrict__ X, const float* __restrict__ RW)
{
    int warp = threadIdx.x >> 5, lane = threadIdx.x & 31;
    int t = blockIdx.x * 8 + warp;
    const float4* X4 = (const float4*)X;
    const float4* RW4 = (const float4*)RW;
    float acc[NEXP];
#pragma unroll
    for (int e = 0; e < NEXP; ++e) acc[e] = 0.f;
#pragma unroll
    for (int it = 0; it < 8; ++it) {
        int h4 = lane + it * 32;
        float4 xv = X4[(size_t)t * 256 + h4];
        int h = h4 * 4;
#pragma unroll
        for (int j = 0; j < 4; ++j) {
            float xs = (j==0)?xv.x:(j==1)?xv.y:(j==2)?xv.z:xv.w;
            float rw[NEXP];
#pragma unroll
            for (int q = 0; q < 4; ++q) {
                float4 rv = RW4[(size_t)(h + j) * 4 + q];
                rw[q*4+0]=rv.x; rw[q*4+1]=rv.y; rw[q*4+2]=rv.z; rw[q*4+3]=rv.w;
            }
#pragma unroll
            for (int e = 0; e < NEXP; ++e) acc[e] += xs * rw[e];
        }
    }
#pragma unroll
    for (int e = 0; e < NEXP; ++e)
#pragma unroll
        for (int off = 16; off > 0; off >>= 1)
            acc[e] += __shfl_xor_sync(0xffffffffu, acc[e], off);
    if (lane == 0) {
        float v[NEXP]; bool used[NEXP];
#pragma unroll
        for (int e = 0; e < NEXP; ++e) { v[e] = 1.f/(1.f+expf(-acc[e])); used[e]=false; }
        for (int k = 0; k < TOPK; ++k) {
            int best=-1; float bv=-1e30f;
            for (int e = 0; e < NEXP; ++e) if (!used[e] && v[e] > bv) { bv=v[e]; best=e; }
            used[best]=true;
            g_topk_idx[t*TOPK+k]=best; g_topk_w[t*TOPK+k]=bv;
        }
    }
}

// ---------------- deterministic compaction ----------------
__global__ void lists_kernel()
{
    __shared__ int s[256];
    int e = blockIdx.x, tid = threadIdx.x, base = 0;
    for (int t0 = 0; t0 < T_TOK; t0 += 256) {
        int t = t0 + tid, kk = -1; float w = 0.f;
#pragma unroll
        for (int k = 0; k < TOPK; ++k)
            if (g_topk_idx[t*TOPK+k] == e) { kk = k; w = g_topk_w[t*TOPK+k]; }
        int flag = (kk >= 0);
        s[tid] = flag; __syncthreads();
        for (int off = 1; off < 256; off <<= 1) {
            int v = (tid >= off) ? s[tid-off] : 0; __syncthreads();
            s[tid] += v; __syncthreads();
        }
        if (flag) { int o = e*T_TOK + base + s[tid]-1; g_tok[o]=t; g_kk[o]=kk; g_wgt[o]=w; }
        base += s[255]; __syncthreads();
    }
    if (tid == 0) g_cnt[e] = base;
}

__global__ void offsets_kernel()
{
    if (threadIdx.x == 0) { int r = 0; for (int e = 0; e < NEXP; ++e) { g_off[e]=r; r+=g_cnt[e]; } }
}

__global__ void invmap_kernel()
{
    int e = blockIdx.x, tid = threadIdx.x;
    int n = g_cnt[e], o = g_off[e];
    for (int i = tid; i < n; i += 256)
        g_inv[g_tok[e*T_TOK+i] * TOPK + g_kk[e*T_TOK+i]] = o + i;
}

// ---------------- convert X to fp16 ----------------
__global__ void convert_x_kernel(const float* __restrict__ X)
{
    int i4 = blockIdx.x * 256 + threadIdx.x;
    float4 v = ((const float4*)X)[i4];
    __half h0 = __float2half(v.x), h1 = __float2half(v.y);
    __half h2 = __float2half(v.z), h3 = __float2half(v.w);
    uint2 p;
    p.x = ((uint32_t)__half_as_ushort(h1) << 16) | __half_as_ushort(h0);
    p.y = ((uint32_t)__half_as_ushort(h3) << 16) | __half_as_ushort(h2);
    ((uint2*)g_xh)[i4] = p;
}

// ---------------- transpose + convert fp16: src[e][R][C] -> dst[e0+e][C][R] ----------------
// grid (C/32, R/128, E), block (32, 8)
__global__ void transpose_h(const float* __restrict__ src,
                            __half* __restrict__ dst, int R, int C, int e0)
{
    __shared__ float tile[128][33];
    int e = blockIdx.z, c0 = blockIdx.x*32, r0 = blockIdx.y*128;
    const float* s = src + (size_t)e * R * C;
    int tx = threadIdx.x, ty = threadIdx.y;
#pragma unroll
    for (int j = 0; j < 16; ++j) {
        int r = ty + j*8;
        tile[r][tx] = s[(size_t)(r0 + r)*C + c0 + tx];
    }
    __syncthreads();
    size_t db = (size_t)(e0 + e) * C * R;
#pragma unroll
    for (int j = 0; j < 4; ++j) {
        int c = ty + j*8;
        float v0 = tile[4*tx+0][c], v1 = tile[4*tx+1][c];
        float v2 = tile[4*tx+2][c], v3 = tile[4*tx+3][c];
        __half h0 = __float2half(v0), h1 = __float2half(v1);
        __half h2 = __float2half(v2), h3 = __float2half(v3);
        uint2 hp;
        hp.x = ((uint32_t)__half_as_ushort(h1)<<16)|__half_as_ushort(h0);
        hp.y = ((uint32_t)__half_as_ushort(h3)<<16)|__half_as_ushort(h2);
        size_t o = db + (size_t)(c0 + c)*R + r0 + 4*tx;
        *(uint2*)(dst + o) = hp;
    }
}

// ---------------- fused gate+up GEMM + SiLU epilogue (1-pass fp16) ----------------
// BM=128, BN=128 both gate & up, BK=64. 512 threads, 4x4 warp grid, 32x32 warp tiles.
// Stage: A 16KB + G 16 + U 16 = 48KB, double buffered.
#define BUFGU 49152
#define DSMGU (2 * BUFGU)
extern __shared__ __align__(1024) char dsm[];

__global__ __launch_bounds__(512, 1) void gemm_gu3()
{
    int e = blockIdx.z;
    bool sh = (e == NEXP);
    int n = sh ? T_TOK : g_cnt[e];
    int m0 = blockIdx.x * 128;
    if (m0 >= n) return;
    int n0 = blockIdx.y * 128;
    int act0 = sh ? RTOT : g_off[e];
    int lbase = e * T_TOK;
    const int K = HDIM;

    __shared__ int s_arow[128];
    int tid = threadIdx.x, wid = tid >> 5, lane = tid & 31;
    if (tid < 128) {
        int m = m0 + tid;
        int mc = (m < n) ? m : (n - 1);
        s_arow[tid] = sh ? mc : g_tok[lbase + mc];
    }
    __syncthreads();

    uint32_t sb = smem_u32(dsm);
    // A loader: 4 threads/row, 2 quads each
    int lr = tid >> 2, aq0 = (tid & 3) * 2;
    const __half* arh = g_xh + (size_t)s_arow[lr] * K;
    // B loader: 2 threads/row; gate (tid<256) / up (tid>=256); 4 quads each
    int br = (tid >> 1) & 127, bq0 = (tid & 1) * 4;
    int isUp = tid >> 8;
    size_t wrow = (size_t)(e * IDIM + n0 + br) * K;
    const __half* bh = (isUp ? g_tu : g_tg) + wrow;
    uint32_t boff = 16384u + (uint32_t)isUp * 16384u;

    auto issue = [&](int c) {
        int k0 = c * 64;
        uint32_t bb = sb + (uint32_t)(c & 1) * BUFGU;
        uint32_t abase = bb + (uint32_t)lr * 128;
#pragma unroll
        for (int j = 0; j < 2; ++j) {
            int q = aq0 + j;
            CP_ASYNC16(abase + (uint32_t)((q ^ (lr & 7)) << 4), arh + k0 + q * 8);
        }
        uint32_t bbase = bb + boff + (uint32_t)br * 128;
#pragma unroll
        for (int j = 0; j < 4; ++j) {
            int q = bq0 + j;
            CP_ASYNC16(bbase + (uint32_t)((q ^ (br & 7)) << 4), bh + k0 + q * 8);
        }
        CP_COMMIT();
    };

    float accG[2][4][4], accU[2][4][4];
#pragma unroll
    for (int mt = 0; mt < 2; ++mt)
#pragma unroll
        for (int nt = 0; nt < 4; ++nt)
#pragma unroll
            for (int q = 0; q < 4; ++q) { accG[mt][nt][q] = 0.f; accU[mt][nt][q] = 0.f; }

    int wr = wid >> 2, wc = wid & 3;          // 4x4 warp grid
    const int NC = K / 64;                    // 16

    issue(0);
    for (int c = 0; c < NC; ++c) {
        if (c + 1 < NC) { issue(c + 1); CP_WAIT1(); }
        else            { CP_WAIT0(); }
        __syncthreads();

        uint32_t bb  = sb + (uint32_t)(c & 1) * BUFGU;
        uint32_t Ahb = bb;
        uint32_t Ghb = bb + 16384, Uhb = bb + 32768;

#pragma unroll
        for (int ks = 0; ks < 4; ++ks) {
            uint32_t afh[2][4], bf[4][2], t4[4];
            int ar = wr * 32 + (lane & 15);
            int aq = 2 * ks + (lane >> 4);
#pragma unroll
            for (int mt = 0; mt < 2; ++mt) {
                int r = ar + mt * 16;
                LDSM_X4(afh[mt], Ahb + (uint32_t)(r * 128 + ((aq ^ (r & 7)) << 4)));
            }
            int br0 = wc * 32 + ((lane >> 4) << 3) + (lane & 7);
            int bq  = 2 * ks + ((lane >> 3) & 1);
            // gate
#pragma unroll
            for (int np = 0; np < 2; ++np) {
                int r = br0 + np * 16;
                LDSM_X4(t4, Ghb + (uint32_t)(r * 128 + ((bq ^ (r & 7)) << 4)));
                bf[np*2][0]=t4[0]; bf[np*2][1]=t4[1]; bf[np*2+1][0]=t4[2]; bf[np*2+1][1]=t4[3];
            }
#pragma unroll
            for (int mt = 0; mt < 2; ++mt)
#pragma unroll
                for (int nt = 0; nt < 4; ++nt)
                    MMA_F16(accG[mt][nt], afh[mt], bf[nt]);
            // up
#pragma unroll
            for (int np = 0; np < 2; ++np) {
                int r = br0 + np * 16;
                LDSM_X4(t4, Uhb + (uint32_t)(r * 128 + ((bq ^ (r & 7)) << 4)));
                bf[np*2][0]=t4[0]; bf[np*2][1]=t4[1]; bf[np*2+1][0]=t4[2]; bf[np*2+1][1]=t4[3];
            }
#pragma unroll
            for (int mt = 0; mt < 2; ++mt)
#pragma unroll
                for (int nt = 0; nt < 4; ++nt)
                    MMA_F16(accU[mt][nt], afh[mt], bf[nt]);
        }
        __syncthreads();
    }

    // epilogue: act = silu(aw*g) * (aw*u) -> fp16
#pragma unroll
    for (int mt = 0; mt < 2; ++mt) {
#pragma unroll
        for (int half = 0; half < 2; ++half) {
            int m = m0 + wr * 32 + mt * 16 + (lane >> 2) + half * 8;
            if (m < n) {
                float aw = sh ? 1.f : g_wgt[lbase + m];
                size_t rowb = (size_t)(act0 + m) * IDIM;
#pragma unroll
                for (int nt = 0; nt < 4; ++nt) {
                    int cc = n0 + wc * 32 + nt * 8 + (lane & 3) * 2;
                    float gv = accG[mt][nt][half*2]   * aw;
                    float uv = accU[mt][nt][half*2]   * aw;
                    float a0 = (gv / (1.f + expf(-gv))) * uv;
                    gv = accG[mt][nt][half*2+1] * aw;
                    uv = accU[mt][nt][half*2+1] * aw;
                    float a1 = (gv / (1.f + expf(-gv))) * uv;
                    __half h0 = __float2half(a0), h1 = __float2half(a1);
                    *(uint32_t*)(g_acth + rowb + cc) =
                        ((uint32_t)__half_as_ushort(h1)<<16) | __half_as_ushort(h0);
                }
            }
        }
    }
}

// ---------------- down GEMM (1-pass fp16), 2 CTAs/SM ----------------
// Stage: A 16KB + B 16KB = 32KB, double buffered = 64KB.
#define BUFSZ 32768
#define DSMEM (2 * BUFSZ)

__global__ __launch_bounds__(256, 2) void gemm3(
    const __half* __restrict__ Ah, const __half* __restrict__ Bh,
    float* __restrict__ C, int K, int N)
{
    int e = blockIdx.z;
    bool sh = (e == NEXP);
    int n = sh ? T_TOK : g_cnt[e];
    int m0 = blockIdx.x * 128;
    if (m0 >= n) return;
    int n0 = blockIdx.y * 128;
    int act0 = sh ? RTOT : g_off[e];
    const __half* Bhe = Bh + (size_t)e * N * K;

    int tid = threadIdx.x, wid = tid >> 5, lane = tid & 31;
    uint32_t sb = smem_u32(dsm);
    int lr = tid >> 1;
    int lq0 = (tid & 1) * 4;
    int mc = (m0 + lr < n) ? (m0 + lr) : (n - 1);
    const __half* arh = Ah + (size_t)(act0 + mc) * K;
    const __half* brh = Bhe + (size_t)(n0 + lr) * K;
    uint32_t swrow = (uint32_t)lr * 128;

    auto issue = [&](int c) {
        int k0 = c * 64;
        uint32_t bb = sb + (uint32_t)(c & 1) * BUFSZ + swrow;
#pragma unroll
        for (int j = 0; j < 4; ++j) {
            int q = lq0 + j;
            uint32_t so = bb + (uint32_t)((q ^ (lr & 7)) << 4);
            CP_ASYNC16(so,          arh + k0 + q * 8);
            CP_ASYNC16(so + 16384,  brh + k0 + q * 8);
        }
        CP_COMMIT();
    };

    float acc[4][4][4];
#pragma unroll
    for (int mt = 0; mt < 4; ++mt)
#pragma unroll
        for (int nt = 0; nt < 4; ++nt)
#pragma unroll
            for (int q = 0; q < 4; ++q) acc[mt][nt][q] = 0.f;

    int wr = wid >> 2, wc = wid & 3;
    int NC = K / 64;

    issue(0);
    for (int c = 0; c < NC; ++c) {
        if (c + 1 < NC) { issue(c + 1); CP_WAIT1(); }
        else            { CP_WAIT0(); }
        __syncthreads();

        uint32_t bb  = sb + (uint32_t)(c & 1) * BUFSZ;
        uint32_t Ahb = bb, Bhb = bb + 16384;

#pragma unroll
        for (int ks = 0; ks < 4; ++ks) {
            uint32_t afh[4][4], bf[4][2], t4[4];
            int ar = wr * 64 + (lane & 15);
            int aq = 2 * ks + (lane >> 4);
#pragma unroll
            for (int mt = 0; mt < 4; ++mt) {
                int r = ar + mt * 16;
                LDSM_X4(afh[mt], Ahb + (uint32_t)(r * 128 + ((aq ^ (r & 7)) << 4)));
            }
            int br0 = wc * 32 + ((lane >> 4) << 3) + (lane & 7);
            int bq  = 2 * ks + ((lane >> 3) & 1);
#pragma unroll
            for (int np = 0; np < 2; ++np) {
                int r = br0 + np * 16;
                LDSM_X4(t4, Bhb + (uint32_t)(r * 128 + ((bq ^ (r & 7)) << 4)));
                bf[np*2][0]=t4[0]; bf[np*2][1]=t4[1]; bf[np*2+1][0]=t4[2]; bf[np*2+1][1]=t4[3];
            }
#pragma unroll
            for (int mt = 0; mt < 4; ++mt)
#pragma unroll
                for (int nt = 0; nt < 4; ++nt)
                    MMA_F16(acc[mt][nt], afh[mt], bf[nt]);
        }
        __syncthreads();
    }

#pragma unroll
    for (int mt = 0; mt < 4; ++mt) {
        int rbase = m0 + wr * 64 + mt * 16 + (lane >> 2);
#pragma unroll
        for (int half = 0; half < 2; ++half) {
            int m = rbase + half * 8;
            if (m < n) {
                float* cp = C + (size_t)(act0 + m) * N + n0 + wc * 32 + (lane & 3) * 2;
#pragma unroll
                for (int nt = 0; nt < 4; ++nt) {
                    float2 v = make_float2(acc[mt][nt][half*2], acc[mt][nt][half*2+1]);
                    *(float2*)(cp + nt * 8) = v;
                }
            }
        }
    }
}

// ---------------- combine ----------------
__global__ void combine_kernel(float* __restrict__ out)
{
    int idx = blockIdx.x * 256 + threadIdx.x;
    int t = idx >> 8, h4 = idx & 255;
    const float4* db = (const float4*)g_dbuf;
    float4 v = db[(size_t)(RTOT + t) * 256 + h4];
#pragma unroll
    for (int k = 0; k < TOPK; ++k) {
        float4 p = db[(size_t)g_inv[t * TOPK + k] * 256 + h4];
        v.x += p.x; v.y += p.y; v.z += p.z; v.w += p.w;
    }
    ((float4*)out)[idx] = v;
}

// ---------------- launch ----------------
extern "C" void kernel_launch(void* const* d_in, const int* in_sizes, int n_in,
                              void* d_out, int out_size)
{
    const float* X  = (const float*)d_in[0];
    const float* RW = (const float*)d_in[1];
    const float* GW = (const float*)d_in[2];
    const float* UW = (const float*)d_in[3];
    const float* DW = (const float*)d_in[4];
    const float* SG = (const float*)d_in[5];
    const float* SU = (const float*)d_in[6];
    const float* SD = (const float*)d_in[7];
    float* out = (float*)d_out;

    cudaFuncSetAttribute(gemm_gu3, cudaFuncAttributeMaxDynamicSharedMemorySize, DSMGU);
    cudaFuncSetAttribute(gemm3,    cudaFuncAttributeMaxDynamicSharedMemorySize, DSMEM);

    __half *tg, *tu, *td, *ah;
    float *dbuf;
    cudaGetSymbolAddress((void**)&tg, g_tg);
    cudaGetSymbolAddress((void**)&tu, g_tu);
    cudaGetSymbolAddress((void**)&td, g_td);
    cudaGetSymbolAddress((void**)&ah, g_acth);
    cudaGetSymbolAddress((void**)&dbuf, g_dbuf);

    router_kernel<<<T_TOK / 8, 256>>>(X, RW);
    lists_kernel<<<NEXP, 256>>>();
    offsets_kernel<<<1, 32>>>();
    invmap_kernel<<<NEXP, 256>>>();
    convert_x_kernel<<<(T_TOK * HDIM) / (4 * 256), 256>>>(X);

    // gate/up: [E][H][I] -> [e][I][H]
    transpose_h<<<dim3(IDIM/32, HDIM/128, NEXP), dim3(32,8)>>>(GW, tg, HDIM, IDIM, 0);
    transpose_h<<<dim3(IDIM/32, HDIM/128, NEXP), dim3(32,8)>>>(UW, tu, HDIM, IDIM, 0);
    transpose_h<<<dim3(IDIM/32, HDIM/128, 1),    dim3(32,8)>>>(SG, tg, HDIM, IDIM, NEXP);
    transpose_h<<<dim3(IDIM/32, HDIM/128, 1),    dim3(32,8)>>>(SU, tu, HDIM, IDIM, NEXP);
    // down: [E][I][H] -> [e][H][I]
    transpose_h<<<dim3(HDIM/32, IDIM/128, NEXP), dim3(32,8)>>>(DW, td, IDIM, HDIM, 0);
    transpose_h<<<dim3(HDIM/32, IDIM/128, 1),    dim3(32,8)>>>(SD, td, IDIM, HDIM, NEXP);

    // fused gate+up + SiLU -> act fp16
    gemm_gu3<<<dim3(T_TOK/128, IDIM/128, NEXP+1), 512, DSMGU>>>();
    // down: act @ Dt -> dbuf
    gemm3<<<dim3(T_TOK/128, HDIM/128, NEXP+1), 256, DSMEM>>>(ah, td, dbuf, IDIM, HDIM);
    combine_kernel<<<(T_TOK * HDIM) / (256 * 4), 256>>>(out);
}